// round 2
// baseline (speedup 1.0000x reference)
#include <cuda_runtime.h>
#include <math.h>

// Problem constants
#define BB 64
#define NN 2048
#define TW 136716        // per-batch weight stride
#define TP 128           // points per CTA
#define PADW 132         // padded point-dim stride in actT (multiple of 4 for LDS.128)
#define KROWS 264        // 258 rows + 6 zero pad rows (K tiles of 8 -> 33 tiles)

// smem layout (floats):
//   actT   [264][132]  transposed activations: actT[k][point]
//   wt     [2][8][256] double-buffered weight tiles (also reused for W0 / W3)
//   cs     [128]       context tile
//   bsm/wscm/bscm/wshm [256] each  (FiLM params per layer)
//   ys     [256]       y tile (layer 0 only)
#define F_ACT   (KROWS * PADW)          // 34848
#define F_WT    (2 * 8 * 256)           // 4096
#define F_CS    128
#define F_FILM  (4 * 256)
#define F_YS    256
#define SMEM_FLOATS (F_ACT + F_WT + F_CS + F_FILM + F_YS)
#define SMEM_BYTES  (SMEM_FLOATS * 4)   // 161408 bytes

__device__ __forceinline__ float sigmoidf_fast(float x) {
    return 1.0f / (1.0f + __expf(-x));
}
__device__ __forceinline__ float softplusf_stable(float x) {
    // log(1+exp(x)) = max(x,0) + log1p(exp(-|x|))
    return fmaxf(x, 0.0f) + log1pf(__expf(-fabsf(x)));
}

__global__ __launch_bounds__(256, 1)
void ode_hypernet_kernel(const float* __restrict__ ctx_g,
                         const float* __restrict__ y_g,
                         const float* __restrict__ yp_g,
                         const float* __restrict__ tnw_g,
                         float* __restrict__ out_g)
{
    extern __shared__ float sm[];
    float* actT = sm;                       // [264][132]
    float* wt   = actT + F_ACT;             // [2][2048]
    float* cs   = wt + F_WT;                // [128]
    float* bsm  = cs + F_CS;                // [256]
    float* wscm = bsm + 256;
    float* bscm = wscm + 256;
    float* wshm = bscm + 256;
    float* ys   = wshm + 256;               // [256]

    const int tid = threadIdx.x;
    const int tx = tid & 15;                // output-dim microtile index
    const int ty = tid >> 4;                // point-dim microtile index
    const int b  = blockIdx.y;
    const int p0 = blockIdx.x * TP;

    const float* w = tnw_g + (size_t)b * TW;

    // ---- initial loads ----
    if (tid < 128) {
        cs[tid] = ctx_g[(size_t)b * NN + p0 + tid];
        size_t base = ((size_t)b * NN + p0 + tid) * 2;
        actT[256 * PADW + tid] = yp_g[base + 0];
        actT[257 * PADW + tid] = yp_g[base + 1];
    }
    // y tile (interleaved y0,y1 per point)
    ys[tid] = y_g[((size_t)b * NN + p0) * 2 + tid];
    // zero pad rows 258..263
    for (int i = tid; i < 6 * PADW; i += 256) actT[258 * PADW + i] = 0.0f;

    // ---- layer 0 params: W0 (4x256) into wt, FiLM params ----
    for (int i = tid; i < 1024; i += 256) wt[i] = w[i];
    bsm[tid]  = w[1024 + tid];
    wscm[tid] = w[1280 + tid];
    bscm[tid] = w[1536 + tid];
    wshm[tid] = w[1792 + tid];
    __syncthreads();

    // ---- layer 0: [y0,y1,yp0,yp1] @ W0 + FiLM + softplus -> actT rows 0..255 ----
    #pragma unroll
    for (int i = 0; i < 8; ++i) {
        int m = ty * 8 + i;
        float y0v = ys[2 * m], y1v = ys[2 * m + 1];
        float q0 = actT[256 * PADW + m];
        float q1 = actT[257 * PADW + m];
        float cc = cs[m];
        #pragma unroll
        for (int c = 0; c < 2; ++c) {
            #pragma unroll
            for (int j = 0; j < 8; ++j) {
                int o = c * 128 + tx * 8 + j;
                float v = y0v * wt[o] + y1v * wt[256 + o]
                        + q0 * wt[512 + o] + q1 * wt[768 + o] + bsm[o];
                float s = sigmoidf_fast(cc * wscm[o] + bscm[o]);
                v = s * v + cc * wshm[o];
                v = softplusf_stable(v);
                actT[o * PADW + m] = v;
            }
        }
    }
    __syncthreads();

    // ---- layers 1 & 2: GEMM 128x256 (K=258) + FiLM + softplus ----
    for (int l = 1; l <= 2; ++l) {
        const float* wl = w + ((l == 1) ? 2048 : 69120);
        const float* fp = wl + 66048;
        bsm[tid]  = fp[tid];
        wscm[tid] = fp[256 + tid];
        bscm[tid] = fp[512 + tid];
        wshm[tid] = fp[768 + tid];

        float acc0[8][8], acc1[8][8];
        #pragma unroll
        for (int i = 0; i < 8; ++i)
            #pragma unroll
            for (int j = 0; j < 8; ++j) { acc0[i][j] = 0.0f; acc1[i][j] = 0.0f; }

        // tile loader: 8 rows x 256 cols, zero rows >= 258
        auto load_tile = [&](float* dst, int t) {
            #pragma unroll
            for (int rep = 0; rep < 2; ++rep) {
                int q  = tid + rep * 256;        // 0..511
                int r  = q >> 6;                 // 0..7
                int cq = (q & 63) << 2;          // 0..252
                int gr = t * 8 + r;
                float4 v = make_float4(0.f, 0.f, 0.f, 0.f);
                if (gr < 258) v = *(const float4*)(wl + gr * 256 + cq);
                *(float4*)(dst + r * 256 + cq) = v;
            }
        };

        load_tile(wt, 0);
        __syncthreads();

        for (int kt = 0; kt < 33; ++kt) {
            float* cur = wt + ((kt & 1) ? 2048 : 0);
            float* nxt = wt + ((kt & 1) ? 0 : 2048);
            if (kt < 32) load_tile(nxt, kt + 1);

            #pragma unroll
            for (int ks = 0; ks < 8; ++ks) {
                const float* arow = &actT[(kt * 8 + ks) * PADW + ty * 8];
                float4 a0 = *(const float4*)arow;
                float4 a1 = *(const float4*)(arow + 4);
                float a[8] = {a0.x, a0.y, a0.z, a0.w, a1.x, a1.y, a1.z, a1.w};
                const float* wr = cur + ks * 256 + tx * 8;
                float4 w0 = *(const float4*)wr;
                float4 w1 = *(const float4*)(wr + 4);
                float4 w2 = *(const float4*)(wr + 128);
                float4 w3 = *(const float4*)(wr + 132);
                float wa[8] = {w0.x, w0.y, w0.z, w0.w, w1.x, w1.y, w1.z, w1.w};
                float wb[8] = {w2.x, w2.y, w2.z, w2.w, w3.x, w3.y, w3.z, w3.w};
                #pragma unroll
                for (int i = 0; i < 8; ++i) {
                    #pragma unroll
                    for (int j = 0; j < 8; ++j) {
                        acc0[i][j] = fmaf(a[i], wa[j], acc0[i][j]);
                        acc1[i][j] = fmaf(a[i], wb[j], acc1[i][j]);
                    }
                }
            }
            __syncthreads();
        }

        // epilogue: FiLM + softplus, write back transposed into actT
        #pragma unroll
        for (int c = 0; c < 2; ++c) {
            #pragma unroll
            for (int j = 0; j < 8; ++j) {
                int o = c * 128 + tx * 8 + j;
                float bi  = bsm[o];
                float wsc = wscm[o];
                float bsc = bscm[o];
                float wsh = wshm[o];
                float vv[8];
                #pragma unroll
                for (int i = 0; i < 8; ++i) {
                    int m = ty * 8 + i;
                    float cc = cs[m];
                    float v = (c == 0 ? acc0[i][j] : acc1[i][j]) + bi;
                    float s = sigmoidf_fast(cc * wsc + bsc);
                    v = s * v + cc * wsh;
                    v = softplusf_stable(v);
                    vv[i] = v;
                }
                float4* dst = (float4*)&actT[o * PADW + ty * 8];
                dst[0] = make_float4(vv[0], vv[1], vv[2], vv[3]);
                dst[1] = make_float4(vv[4], vv[5], vv[6], vv[7]);
            }
        }
        __syncthreads();
    }

    // ---- layer 3: [128 pts][258] @ W3[258][2] + FiLM (no softplus) -> out ----
    for (int i = tid; i < 516; i += 256) wt[i] = w[136192 + i];
    if (tid < 2) {
        bsm[tid]  = w[136708 + tid];
        wscm[tid] = w[136710 + tid];
        bscm[tid] = w[136712 + tid];
        wshm[tid] = w[136714 + tid];
    }
    __syncthreads();

    {
        int p = tid >> 1;
        int o = tid & 1;
        float cc = cs[p];
        float sum = 0.0f;
        #pragma unroll 4
        for (int k = 0; k < 258; ++k)
            sum = fmaf(actT[k * PADW + p], wt[2 * k + o], sum);
        float v = sum + bsm[o];
        float s = sigmoidf_fast(cc * wscm[o] + bscm[o]);
        v = s * v + cc * wshm[o];
        out_g[((size_t)b * NN + p0 + p) * 2 + o] = v;
    }
}

extern "C" void kernel_launch(void* const* d_in, const int* in_sizes, int n_in,
                              void* d_out, int out_size) {
    (void)in_sizes; (void)n_in; (void)out_size;
    const float* ctx = (const float*)d_in[0];   // context [64,2048]
    const float* y   = (const float*)d_in[1];   // y       [64,2048,2]
    const float* yp  = (const float*)d_in[2];   // y_points[64,2048,2]
    const float* tnw = (const float*)d_in[3];   // weights [64,136716]
    float* out = (float*)d_out;                 // [64,2048,2]

    cudaFuncSetAttribute(ode_hypernet_kernel,
                         cudaFuncAttributeMaxDynamicSharedMemorySize, SMEM_BYTES);
    dim3 grid(NN / TP, BB);   // (16, 64)
    ode_hypernet_kernel<<<grid, 256, SMEM_BYTES>>>(ctx, y, yp, tnw, out);
}

// round 3
// speedup vs baseline: 1.2975x; 1.2975x over previous
#include <cuda_runtime.h>
#include <math.h>

// Problem constants
#define BB 64
#define NN 2048
#define TW 136716        // per-batch weight stride
#define TP 128           // points per CTA
#define PADW 132         // padded point-dim stride in actT (16B-aligned rows)
#define KROWS 264        // 258 rows + 6 zero pad rows (K tiles of 8 -> 33 tiles)

#define F_ACT   (KROWS * PADW)          // 34848
#define F_WT    (2 * 8 * 256)           // 4096 (double-buffered weight tiles; reused as reduction buffer)
#define F_CS    128
#define F_FILM  (4 * 256)
#define F_YS    256
#define F_W3    524                     // W3 (516) + film3 (8)
#define SMEM_FLOATS (F_ACT + F_WT + F_CS + F_FILM + F_YS + F_W3)
#define SMEM_BYTES  (SMEM_FLOATS * 4)

typedef unsigned long long u64t;

__device__ __forceinline__ void ffma2(u64t& d, u64t a, u64t b) {
    asm("fma.rn.f32x2 %0, %1, %2, %0;" : "+l"(d) : "l"(a), "l"(b));
}
__device__ __forceinline__ u64t dup2(float x) {
    u64t r; asm("mov.b64 %0, {%1, %1};" : "=l"(r) : "f"(x)); return r;
}
__device__ __forceinline__ float2 unpk(u64t v) {
    float2 r; asm("mov.b64 {%0, %1}, %2;" : "=f"(r.x), "=f"(r.y) : "l"(v)); return r;
}
__device__ __forceinline__ float ex2f(float x){ float r; asm("ex2.approx.ftz.f32 %0, %1;" : "=f"(r) : "f"(x)); return r; }
__device__ __forceinline__ float lg2f(float x){ float r; asm("lg2.approx.ftz.f32 %0, %1;" : "=f"(r) : "f"(x)); return r; }
__device__ __forceinline__ float rcpf(float x){ float r; asm("rcp.approx.ftz.f32 %0, %1;" : "=f"(r) : "f"(x)); return r; }

__device__ __forceinline__ float sigmoidf_fast(float x) {
    return rcpf(1.0f + ex2f(-1.4426950408889634f * x));
}
__device__ __forceinline__ float softplusf_fast(float x) {
    // max(x,0) + ln2 * log2(1 + 2^(-|x|*log2e))
    float e = ex2f(-1.4426950408889634f * fabsf(x));
    return fmaxf(x, 0.0f) + 0.6931471805599453f * lg2f(1.0f + e);
}

__global__ __launch_bounds__(256, 1)
void ode_hypernet_kernel(const float* __restrict__ ctx_g,
                         const float* __restrict__ y_g,
                         const float* __restrict__ yp_g,
                         const float* __restrict__ tnw_g,
                         float* __restrict__ out_g)
{
    extern __shared__ float sm[];
    float* actT = sm;                       // [264][132]
    float* wt   = actT + F_ACT;             // [2][2048]; reused as red[16][128][2] at the end
    float* cs   = wt + F_WT;                // [128]
    float* bsm  = cs + F_CS;                // [256]
    float* wscm = bsm + 256;
    float* bscm = wscm + 256;
    float* wshm = bscm + 256;
    float* ys   = wshm + 256;               // [256]
    float* w3s  = ys + F_YS;                // [516] W3 + [8] film3

    const int tid = threadIdx.x;
    const int tx = tid & 15;                // output-dim microtile index
    const int ty = tid >> 4;                // point-dim microtile index
    const int b  = blockIdx.y;
    const int p0 = blockIdx.x * TP;

    const float* w = tnw_g + (size_t)b * TW;

    // ---- initial loads ----
    if (tid < 128) {
        cs[tid] = ctx_g[(size_t)b * NN + p0 + tid];
        size_t base = ((size_t)b * NN + p0 + tid) * 2;
        actT[256 * PADW + tid] = yp_g[base + 0];
        actT[257 * PADW + tid] = yp_g[base + 1];
    }
    ys[tid] = y_g[((size_t)b * NN + p0) * 2 + tid];
    for (int i = tid; i < 6 * PADW; i += 256) actT[258 * PADW + i] = 0.0f;

    // ---- layer 0 params + W3/film3 (loaded once, used at the very end) ----
    for (int i = tid; i < 1024; i += 256) wt[i] = w[i];
    for (int i = tid; i < 516; i += 256)  w3s[i] = w[136192 + i];
    if (tid < 8) w3s[516 + tid] = w[136708 + tid];
    bsm[tid]  = w[1024 + tid];
    wscm[tid] = w[1280 + tid];
    bscm[tid] = w[1536 + tid];
    wshm[tid] = w[1792 + tid];
    __syncthreads();

    // ---- layer 0: [y0,y1,yp0,yp1] @ W0 + FiLM + softplus -> actT rows 0..255 ----
    #pragma unroll
    for (int i = 0; i < 8; ++i) {
        int m = ty * 8 + i;
        float y0v = ys[2 * m], y1v = ys[2 * m + 1];
        float q0 = actT[256 * PADW + m];
        float q1 = actT[257 * PADW + m];
        float cc = cs[m];
        #pragma unroll
        for (int c = 0; c < 2; ++c) {
            #pragma unroll
            for (int j = 0; j < 8; ++j) {
                int o = c * 128 + tx * 8 + j;
                float v = y0v * wt[o] + y1v * wt[256 + o]
                        + q0 * wt[512 + o] + q1 * wt[768 + o] + bsm[o];
                float s = sigmoidf_fast(cc * wscm[o] + bscm[o]);
                v = s * v + cc * wshm[o];
                v = softplusf_fast(v);
                actT[o * PADW + m] = v;
            }
        }
    }
    __syncthreads();

    // per-thread partials of the final 258->2 projection (filled by layer-2 epilogue)
    float ps0[8], ps1[8];

    // ---- layers 1 & 2: GEMM 128x256 (K=258) + FiLM + softplus ----
    #pragma unroll 1
    for (int l = 1; l <= 2; ++l) {
        const float* wl = w + ((l == 1) ? 2048 : 69120);
        const float* fp = wl + 66048;
        bsm[tid]  = fp[tid];
        wscm[tid] = fp[256 + tid];
        bscm[tid] = fp[512 + tid];
        wshm[tid] = fp[768 + tid];

        u64t accA[8][4], accB[8][4];
        #pragma unroll
        for (int i = 0; i < 8; ++i)
            #pragma unroll
            for (int jp = 0; jp < 4; ++jp) { accA[i][jp] = 0ull; accB[i][jp] = 0ull; }

        // tile loader: 8 rows x 256 cols, zero rows >= 258
        auto load_tile = [&](float* dst, int t) {
            #pragma unroll
            for (int rep = 0; rep < 2; ++rep) {
                int q  = tid + rep * 256;        // 0..511
                int r  = q >> 6;                 // 0..7
                int cq = (q & 63) << 2;          // 0..252
                int gr = t * 8 + r;
                float4 v = make_float4(0.f, 0.f, 0.f, 0.f);
                if (gr < 258) v = *(const float4*)(wl + gr * 256 + cq);
                *(float4*)(dst + r * 256 + cq) = v;
            }
        };

        load_tile(wt, 0);
        __syncthreads();

        for (int kt = 0; kt < 33; ++kt) {
            float* cur = wt + ((kt & 1) ? 2048 : 0);
            float* nxt = wt + ((kt & 1) ? 0 : 2048);
            if (kt < 32) load_tile(nxt, kt + 1);

            #pragma unroll
            for (int ks = 0; ks < 8; ++ks) {
                const float* arow = &actT[(kt * 8 + ks) * PADW + ty * 8];
                float4 a0 = *(const float4*)arow;
                float4 a1 = *(const float4*)(arow + 4);
                u64t ad[8] = {dup2(a0.x), dup2(a0.y), dup2(a0.z), dup2(a0.w),
                              dup2(a1.x), dup2(a1.y), dup2(a1.z), dup2(a1.w)};
                const ulonglong2* wr = (const ulonglong2*)(cur + ks * 256 + tx * 8);
                ulonglong2 wA0 = wr[0], wA1 = wr[1];     // cols tx*8 .. tx*8+7
                ulonglong2 wB0 = wr[32], wB1 = wr[33];   // cols 128+tx*8 ..
                u64t wa[4] = {wA0.x, wA0.y, wA1.x, wA1.y};
                u64t wb[4] = {wB0.x, wB0.y, wB1.x, wB1.y};
                #pragma unroll
                for (int i = 0; i < 8; ++i) {
                    #pragma unroll
                    for (int jp = 0; jp < 4; ++jp) {
                        ffma2(accA[i][jp], ad[i], wa[jp]);
                        ffma2(accB[i][jp], ad[i], wb[jp]);
                    }
                }
            }
            __syncthreads();
        }

        if (l == 1) {
            // epilogue: FiLM + softplus, write back transposed into actT
            #pragma unroll
            for (int c = 0; c < 2; ++c) {
                #pragma unroll
                for (int jp = 0; jp < 4; ++jp) {
                    float vv0[8], vv1[8];
                    int o0 = c * 128 + tx * 8 + jp * 2;
                    float bi0  = bsm[o0],      bi1  = bsm[o0 + 1];
                    float wsc0 = wscm[o0],     wsc1 = wscm[o0 + 1];
                    float bsc0 = bscm[o0],     bsc1 = bscm[o0 + 1];
                    float wsh0 = wshm[o0],     wsh1 = wshm[o0 + 1];
                    #pragma unroll
                    for (int i = 0; i < 8; ++i) {
                        int m = ty * 8 + i;
                        float cc = cs[m];
                        float2 v = unpk(c == 0 ? accA[i][jp] : accB[i][jp]);
                        float x0 = v.x + bi0;
                        float x1 = v.y + bi1;
                        x0 = sigmoidf_fast(cc * wsc0 + bsc0) * x0 + cc * wsh0;
                        x1 = sigmoidf_fast(cc * wsc1 + bsc1) * x1 + cc * wsh1;
                        vv0[i] = softplusf_fast(x0);
                        vv1[i] = softplusf_fast(x1);
                    }
                    float4* d0 = (float4*)&actT[o0 * PADW + ty * 8];
                    d0[0] = make_float4(vv0[0], vv0[1], vv0[2], vv0[3]);
                    d0[1] = make_float4(vv0[4], vv0[5], vv0[6], vv0[7]);
                    float4* d1 = (float4*)&actT[(o0 + 1) * PADW + ty * 8];
                    d1[0] = make_float4(vv1[0], vv1[1], vv1[2], vv1[3]);
                    d1[1] = make_float4(vv1[4], vv1[5], vv1[6], vv1[7]);
                }
            }
            __syncthreads();
        } else {
            // layer-2 epilogue fused with layer-3 partial projection:
            // no actT writeback; accumulate ps[o] += act2 * W3[k][o] over this
            // thread's 16 channels.
            #pragma unroll
            for (int i = 0; i < 8; ++i) { ps0[i] = 0.0f; ps1[i] = 0.0f; }
            #pragma unroll
            for (int c = 0; c < 2; ++c) {
                #pragma unroll
                for (int jp = 0; jp < 4; ++jp) {
                    int o0 = c * 128 + tx * 8 + jp * 2;
                    float bi0  = bsm[o0],      bi1  = bsm[o0 + 1];
                    float wsc0 = wscm[o0],     wsc1 = wscm[o0 + 1];
                    float bsc0 = bscm[o0],     bsc1 = bscm[o0 + 1];
                    float wsh0 = wshm[o0],     wsh1 = wshm[o0 + 1];
                    float w3_00 = w3s[2 * o0 + 0], w3_01 = w3s[2 * o0 + 1];
                    float w3_10 = w3s[2 * o0 + 2], w3_11 = w3s[2 * o0 + 3];
                    #pragma unroll
                    for (int i = 0; i < 8; ++i) {
                        int m = ty * 8 + i;
                        float cc = cs[m];
                        float2 v = unpk(c == 0 ? accA[i][jp] : accB[i][jp]);
                        float x0 = v.x + bi0;
                        float x1 = v.y + bi1;
                        x0 = sigmoidf_fast(cc * wsc0 + bsc0) * x0 + cc * wsh0;
                        x1 = sigmoidf_fast(cc * wsc1 + bsc1) * x1 + cc * wsh1;
                        x0 = softplusf_fast(x0);
                        x1 = softplusf_fast(x1);
                        ps0[i] = fmaf(x0, w3_00, fmaf(x1, w3_10, ps0[i]));
                        ps1[i] = fmaf(x0, w3_01, fmaf(x1, w3_11, ps1[i]));
                    }
                }
            }
        }
    }

    // ---- 16-way reduction of layer-3 partials through smem (reusing wt) ----
    // red[tx][p][o] : index tx*256 + p*2 + o
    {
        float2* red = (float2*)wt;
        #pragma unroll
        for (int i = 0; i < 8; ++i)
            red[tx * 128 + ty * 8 + i] = make_float2(ps0[i], ps1[i]);
    }
    __syncthreads();

    {
        int p = tid >> 1;
        int o = tid & 1;
        float sum = 0.0f;
        #pragma unroll
        for (int t = 0; t < 16; ++t)
            sum += wt[t * 256 + p * 2 + o];
        // yp contribution (channels 256, 257 of the concat)
        float q0 = actT[256 * PADW + p];
        float q1 = actT[257 * PADW + p];
        sum = fmaf(q0, w3s[512 + o], sum);
        sum = fmaf(q1, w3s[514 + o], sum);
        float cc = cs[p];
        float v = sum + w3s[516 + o];
        float s = sigmoidf_fast(cc * w3s[518 + o] + w3s[520 + o]);
        v = s * v + cc * w3s[522 + o];
        out_g[((size_t)b * NN + p0 + p) * 2 + o] = v;
    }
}

extern "C" void kernel_launch(void* const* d_in, const int* in_sizes, int n_in,
                              void* d_out, int out_size) {
    (void)in_sizes; (void)n_in; (void)out_size;
    const float* ctx = (const float*)d_in[0];   // context [64,2048]
    const float* y   = (const float*)d_in[1];   // y       [64,2048,2]
    const float* yp  = (const float*)d_in[2];   // y_points[64,2048,2]
    const float* tnw = (const float*)d_in[3];   // weights [64,136716]
    float* out = (float*)d_out;                 // [64,2048,2]

    cudaFuncSetAttribute(ode_hypernet_kernel,
                         cudaFuncAttributeMaxDynamicSharedMemorySize, SMEM_BYTES);
    dim3 grid(NN / TP, BB);   // (16, 64)
    ode_hypernet_kernel<<<grid, 256, SMEM_BYTES>>>(ctx, y, yp, tnw, out);
}

// round 5
// speedup vs baseline: 2.7323x; 2.1058x over previous
#include <cuda_runtime.h>
#include <cuda_bf16.h>
#include <cstdint>

typedef unsigned int u32;

// ---------------- problem constants ----------------
#define BB 64
#define NN 2048
#define TW 136716
#define TP 128

// ---------------- smem layout (bytes) ----------------
#define SM_AHI 0
#define SM_ALO 65536
#define SM_B   131072        // [2 buf][2 h][16384]
#define SM_PAR 196608
// float offsets inside PAR
#define PF_FILM  0
#define PF_WTAIL 1024
#define PF_W3    1536
#define PF_CS    2064
#define PF_YPX   2192
#define PF_YPY   2320
#define PF_YS    2448
#define PF_W0    2704
#define PF_RED   3728
#define SMEM_TOTAL (196608 + 3984*4)

// precomputed bf16 weights: [b][l][h][kc 8][swizzled 16KB chunk] = 32 MB
__device__ uint4 g_wbf[2097152];

// ---------------- helpers ----------------
__device__ __forceinline__ u32 smem_u32(const void* p) {
    u32 a; asm("{ .reg .u64 t; cvta.to.shared.u64 t, %1; cvt.u32.u64 %0, t; }" : "=r"(a) : "l"(p));
    return a;
}
__device__ __forceinline__ u32 pack_bf2(float a, float b) {
    __nv_bfloat162 t = __floats2bfloat162_rn(a, b);
    return *reinterpret_cast<u32*>(&t);
}
__device__ __forceinline__ void ldsm4(u32& r0, u32& r1, u32& r2, u32& r3, u32 addr) {
    asm volatile("ldmatrix.sync.aligned.m8n8.x4.shared.b16 {%0,%1,%2,%3}, [%4];"
                 : "=r"(r0), "=r"(r1), "=r"(r2), "=r"(r3) : "r"(addr));
}
__device__ __forceinline__ void mma16816(float& c0, float& c1, float& c2, float& c3,
                                         u32 a0, u32 a1, u32 a2, u32 a3,
                                         u32 b0, u32 b1) {
    asm volatile("mma.sync.aligned.m16n8k16.row.col.f32.bf16.bf16.f32 "
                 "{%0,%1,%2,%3}, {%4,%5,%6,%7}, {%8,%9}, {%0,%1,%2,%3};"
                 : "+f"(c0), "+f"(c1), "+f"(c2), "+f"(c3)
                 : "r"(a0), "r"(a1), "r"(a2), "r"(a3), "r"(b0), "r"(b1));
}
__device__ __forceinline__ float ex2f(float x){ float r; asm("ex2.approx.ftz.f32 %0, %1;" : "=f"(r) : "f"(x)); return r; }
__device__ __forceinline__ float lg2f(float x){ float r; asm("lg2.approx.ftz.f32 %0, %1;" : "=f"(r) : "f"(x)); return r; }
__device__ __forceinline__ float rcpf(float x){ float r; asm("rcp.approx.ftz.f32 %0, %1;" : "=f"(r) : "f"(x)); return r; }
__device__ __forceinline__ float sigmoidf_fast(float x) {
    return rcpf(1.0f + ex2f(-1.4426950408889634f * x));
}
__device__ __forceinline__ float softplusf_fast(float x) {
    float e = ex2f(-1.4426950408889634f * fabsf(x));
    return fmaxf(x, 0.0f) + 0.6931471805599453f * lg2f(1.0f + e);
}

// A smem byte address: row-major 512B rows, 16B-unit XOR swizzle on bits 4-6
__device__ __forceinline__ u32 a_byte(int row, u32 kb) {
    return (u32)row * 512 + (kb ^ (((u32)row & 7) << 4));
}

// ---------------- prep kernel: f32 W -> bf16 hi/lo swizzled chunk images ----------------
__global__ __launch_bounds__(256)
void prep_weights_kernel(const float* __restrict__ tnw)
{
    __shared__ float s[32 * 257];
    int blkid = blockIdx.x;          // bl(0..127)*8 + ntile
    int nt = blkid & 7;
    int bl = blkid >> 3;
    int l = bl & 1;
    int b = bl >> 1;
    int n0 = nt * 32;
    const float* wl = tnw + (size_t)b * TW + (l == 0 ? 2048 : 69120);
    int t = threadIdx.x;

    // load W[k][n0..n0+31] -> s[n][k]
    int kq = t >> 5;     // 0..7
    int nq = t & 31;
    for (int kk = 0; kk < 256; kk += 8)
        s[nq * 257 + kk + kq] = wl[(size_t)(kk + kq) * 256 + n0 + nq];
    __syncthreads();

    // write swizzled chunks: thread (n = t&31, chunk seg = t>>5)
    int n = t & 31;
    int seg = t >> 5;        // kc 0..7
    int nG = n0 + n;
    u32 xr = (((u32)nG >> 1) & 3) << 4;
    char* gw = (char*)g_wbf;
    size_t base0 = (size_t)((b * 2 + l) * 2 + 0) * 131072 + (size_t)seg * 16384
                 + (size_t)(nG >> 1) * 128 + (size_t)(nG & 1) * 64;
    size_t base1 = base0 + 131072;
    #pragma unroll
    for (int u = 0; u < 4; ++u) {
        u32 hi[4], lo[4];
        #pragma unroll
        for (int j = 0; j < 4; ++j) {
            float v0 = s[n * 257 + seg * 32 + u * 8 + 2 * j];
            float v1 = s[n * 257 + seg * 32 + u * 8 + 2 * j + 1];
            float h0 = __bfloat162float(__float2bfloat16_rn(v0));
            float h1 = __bfloat162float(__float2bfloat16_rn(v1));
            hi[j] = pack_bf2(v0, v1);
            lo[j] = pack_bf2(v0 - h0, v1 - h1);
        }
        u32 off = ((u32)(u * 16)) ^ xr;
        *(uint4*)(gw + base0 + off) = make_uint4(hi[0], hi[1], hi[2], hi[3]);
        *(uint4*)(gw + base1 + off) = make_uint4(lo[0], lo[1], lo[2], lo[3]);
    }
}

// ---------------- main kernel ----------------
__global__ __launch_bounds__(256, 1)
void ode_hypernet_mma_kernel(const float* __restrict__ ctx_g,
                             const float* __restrict__ y_g,
                             const float* __restrict__ yp_g,
                             const float* __restrict__ tnw_g,
                             float* __restrict__ out_g)
{
    extern __shared__ char smc[];
    float* par = (float*)(smc + SM_PAR);
    const u32 smb = smem_u32(smc);

    const int tid = threadIdx.x;
    const int lid = tid & 31;
    const int wid = tid >> 5;
    const int wm = wid & 1;          // m-half (64 rows)
    const int wn = wid >> 1;         // n-quarter (64 cols)
    const int b  = blockIdx.y;
    const int p0 = blockIdx.x * TP;
    const float* w = tnw_g + (size_t)b * TW;

    // ---- initial loads ----
    if (tid < 128) {
        par[PF_CS + tid] = ctx_g[(size_t)b * NN + p0 + tid];
        size_t base = ((size_t)b * NN + p0 + tid) * 2;
        par[PF_YPX + tid] = yp_g[base + 0];
        par[PF_YPY + tid] = yp_g[base + 1];
    }
    par[PF_YS + tid] = y_g[((size_t)b * NN + p0) * 2 + tid];
    #pragma unroll
    for (int i = 0; i < 4; ++i) par[PF_W0 + i * 256 + tid] = w[i * 256 + tid];
    #pragma unroll
    for (int i = 0; i < 4; ++i) par[PF_FILM + i * 256 + tid] = w[1024 + i * 256 + tid];
    for (int i = tid; i < 524; i += 256) par[PF_W3 + i] = w[136192 + i];
    __syncthreads();

    // ---- layer 0 (SIMT): 4 -> 256, FiLM + softplus, write A hi/lo ----
    {
        int p = tid & 127;
        int h = tid >> 7;
        float y0 = par[PF_YS + 2 * p], y1 = par[PF_YS + 2 * p + 1];
        float q0 = par[PF_YPX + p],    q1 = par[PF_YPY + p];
        float cc = par[PF_CS + p];
        #pragma unroll 4
        for (int j = 0; j < 64; ++j) {
            int ch = h * 128 + 2 * j;
            float v0 = y0 * par[PF_W0 + ch]       + y1 * par[PF_W0 + 256 + ch]
                     + q0 * par[PF_W0 + 512 + ch] + q1 * par[PF_W0 + 768 + ch]
                     + par[PF_FILM + ch];
            float v1 = y0 * par[PF_W0 + ch + 1]       + y1 * par[PF_W0 + 256 + ch + 1]
                     + q0 * par[PF_W0 + 512 + ch + 1] + q1 * par[PF_W0 + 768 + ch + 1]
                     + par[PF_FILM + ch + 1];
            float s0 = sigmoidf_fast(cc * par[PF_FILM + 256 + ch]     + par[PF_FILM + 512 + ch]);
            float s1 = sigmoidf_fast(cc * par[PF_FILM + 256 + ch + 1] + par[PF_FILM + 512 + ch + 1]);
            v0 = s0 * v0 + cc * par[PF_FILM + 768 + ch];
            v1 = s1 * v1 + cc * par[PF_FILM + 768 + ch + 1];
            v0 = softplusf_fast(v0);
            v1 = softplusf_fast(v1);
            u32 byte = a_byte(p, (u32)(2 * ch));
            float h0 = __bfloat162float(__float2bfloat16_rn(v0));
            float h1 = __bfloat162float(__float2bfloat16_rn(v1));
            *(u32*)(smc + SM_AHI + byte) = pack_bf2(v0, v1);
            *(u32*)(smc + SM_ALO + byte) = pack_bf2(v0 - h0, v1 - h1);
        }
    }
    __syncthreads();

    // ---- per-thread ldmatrix address constants ----
    u32 abase_[4], axor_[4];
    #pragma unroll
    for (int mi = 0; mi < 4; ++mi) {
        int arow = wm * 64 + mi * 16 + (lid & 15);
        abase_[mi] = (u32)arow * 512;
        axor_[mi]  = ((u32)arow & 7) << 4;
    }
    const u32 aksel = ((u32)(lid >> 4) & 1) << 4;
    u32 bbase_[4], bxor_[4];
    #pragma unroll
    for (int nt = 0; nt < 4; ++nt) {
        int brow = wn * 64 + nt * 16 + (lid & 7) + ((lid & 16) >> 1);
        bbase_[nt] = ((u32)(brow >> 1)) * 128 + ((u32)brow & 1) * 64;
        bxor_[nt]  = (((u32)brow >> 1) & 3) << 4;
    }
    const u32 bksel = ((u32)(lid >> 3) & 1) << 4;

    float ps0[8], ps1[8];   // fused layer-3 partials

    #pragma unroll 1
    for (int l = 1; l <= 2; ++l) {
        const float* wl = w + ((l == 1) ? 2048 : 69120);
        const float* fp = wl + 66048;
        #pragma unroll
        for (int i = 0; i < 4; ++i) par[PF_FILM + i * 256 + tid] = fp[i * 256 + tid];
        par[PF_WTAIL + tid]       = wl[65536 + tid];
        par[PF_WTAIL + 256 + tid] = wl[65792 + tid];

        float acc[4][8][4];
        #pragma unroll
        for (int mi = 0; mi < 4; ++mi)
            #pragma unroll
            for (int n8 = 0; n8 < 8; ++n8)
                #pragma unroll
                for (int q = 0; q < 4; ++q) acc[mi][n8][q] = 0.0f;

        // chunk loader: flat 32KB copy (prep already swizzled)
        const char* gw = (const char*)g_wbf;
        size_t lbase = (size_t)((b * 2 + (l - 1)) * 2) * 131072;
        auto load_chunk = [&](int kc, int buf) {
            const uint4* s0 = (const uint4*)(gw + lbase + (size_t)kc * 16384);
            const uint4* s1 = (const uint4*)(gw + lbase + 131072 + (size_t)kc * 16384);
            uint4* dh = (uint4*)(smc + SM_B + buf * 32768);
            uint4* dl = (uint4*)(smc + SM_B + buf * 32768 + 16384);
            #pragma unroll
            for (int i = 0; i < 4; ++i) {
                dh[tid + i * 256] = s0[tid + i * 256];
                dl[tid + i * 256] = s1[tid + i * 256];
            }
        };

        load_chunk(0, 0);
        __syncthreads();

        #pragma unroll 1
        for (int kc = 0; kc < 8; ++kc) {
            int buf = kc & 1;
            if (kc < 7) load_chunk(kc + 1, buf ^ 1);

            #pragma unroll
            for (int ks = 0; ks < 2; ++ks) {
                u32 kbA = (u32)(kc * 64 + ks * 32);
                u32 ah[4][4], al[4][4];
                #pragma unroll
                for (int mi = 0; mi < 4; ++mi) {
                    u32 off = abase_[mi] + ((kbA + aksel) ^ axor_[mi]);
                    ldsm4(ah[mi][0], ah[mi][1], ah[mi][2], ah[mi][3], smb + SM_AHI + off);
                    ldsm4(al[mi][0], al[mi][1], al[mi][2], al[mi][3], smb + SM_ALO + off);
                }
                u32 bh[4][4], bl[4][4];
                u32 hb = smb + SM_B + (u32)buf * 32768;
                #pragma unroll
                for (int nt = 0; nt < 4; ++nt) {
                    u32 off = bbase_[nt] + (((u32)(ks * 32) + bksel) ^ bxor_[nt]);
                    ldsm4(bh[nt][0], bh[nt][1], bh[nt][2], bh[nt][3], hb + off);
                    ldsm4(bl[nt][0], bl[nt][1], bl[nt][2], bl[nt][3], hb + 16384 + off);
                }
                // term 1: Ahi * Bhi
                #pragma unroll
                for (int mi = 0; mi < 4; ++mi)
                    #pragma unroll
                    for (int n8 = 0; n8 < 8; ++n8) {
                        int nt = n8 >> 1, pp = (n8 & 1) * 2;
                        mma16816(acc[mi][n8][0], acc[mi][n8][1], acc[mi][n8][2], acc[mi][n8][3],
                                 ah[mi][0], ah[mi][1], ah[mi][2], ah[mi][3],
                                 bh[nt][pp], bh[nt][pp + 1]);
                    }
                // term 2: Ahi * Blo
                #pragma unroll
                for (int mi = 0; mi < 4; ++mi)
                    #pragma unroll
                    for (int n8 = 0; n8 < 8; ++n8) {
                        int nt = n8 >> 1, pp = (n8 & 1) * 2;
                        mma16816(acc[mi][n8][0], acc[mi][n8][1], acc[mi][n8][2], acc[mi][n8][3],
                                 ah[mi][0], ah[mi][1], ah[mi][2], ah[mi][3],
                                 bl[nt][pp], bl[nt][pp + 1]);
                    }
                // term 3: Alo * Bhi
                #pragma unroll
                for (int mi = 0; mi < 4; ++mi)
                    #pragma unroll
                    for (int n8 = 0; n8 < 8; ++n8) {
                        int nt = n8 >> 1, pp = (n8 & 1) * 2;
                        mma16816(acc[mi][n8][0], acc[mi][n8][1], acc[mi][n8][2], acc[mi][n8][3],
                                 al[mi][0], al[mi][1], al[mi][2], al[mi][3],
                                 bh[nt][pp], bh[nt][pp + 1]);
                    }
            }
            __syncthreads();
        }

        if (l == 2) {
            // zero the layer-3 reduction buffer before atomics
            par[PF_RED + tid] = 0.0f;
            #pragma unroll
            for (int i = 0; i < 8; ++i) { ps0[i] = 0.0f; ps1[i] = 0.0f; }
            __syncthreads();
        }

        // ---- epilogue ----
        #pragma unroll
        for (int n8 = 0; n8 < 8; ++n8) {
            int col0 = wn * 64 + n8 * 8 + (lid & 3) * 2;
            int col1 = col0 + 1;
            float bi0  = par[PF_FILM + col0],       bi1  = par[PF_FILM + col1];
            float wsc0 = par[PF_FILM + 256 + col0], wsc1 = par[PF_FILM + 256 + col1];
            float bsc0 = par[PF_FILM + 512 + col0], bsc1 = par[PF_FILM + 512 + col1];
            float wsh0 = par[PF_FILM + 768 + col0], wsh1 = par[PF_FILM + 768 + col1];
            float wt00 = par[PF_WTAIL + col0],       wt01 = par[PF_WTAIL + col1];
            float wt10 = par[PF_WTAIL + 256 + col0], wt11 = par[PF_WTAIL + 256 + col1];
            float w300 = 0.f, w301 = 0.f, w310 = 0.f, w311 = 0.f;
            if (l == 2) {
                w300 = par[PF_W3 + 2 * col0];     w301 = par[PF_W3 + 2 * col0 + 1];
                w310 = par[PF_W3 + 2 * col1];     w311 = par[PF_W3 + 2 * col1 + 1];
            }
            #pragma unroll
            for (int mi = 0; mi < 4; ++mi) {
                #pragma unroll
                for (int rh = 0; rh < 2; ++rh) {
                    int row = wm * 64 + mi * 16 + (lid >> 2) + rh * 8;
                    float cc = par[PF_CS + row];
                    float q0 = par[PF_YPX + row], q1 = par[PF_YPY + row];
                    float v0 = acc[mi][n8][rh * 2 + 0];
                    float v1 = acc[mi][n8][rh * 2 + 1];
                    v0 += bi0 + q0 * wt00 + q1 * wt10;
                    v1 += bi1 + q0 * wt01 + q1 * wt11;
                    float s0 = sigmoidf_fast(cc * wsc0 + bsc0);
                    float s1 = sigmoidf_fast(cc * wsc1 + bsc1);
                    v0 = s0 * v0 + cc * wsh0;
                    v1 = s1 * v1 + cc * wsh1;
                    v0 = softplusf_fast(v0);
                    v1 = softplusf_fast(v1);
                    if (l == 1) {
                        u32 byte = a_byte(row, (u32)(2 * col0));
                        float h0 = __bfloat162float(__float2bfloat16_rn(v0));
                        float h1 = __bfloat162float(__float2bfloat16_rn(v1));
                        *(u32*)(smc + SM_AHI + byte) = pack_bf2(v0, v1);
                        *(u32*)(smc + SM_ALO + byte) = pack_bf2(v0 - h0, v1 - h1);
                    } else {
                        ps0[mi * 2 + rh] = fmaf(v0, w300, fmaf(v1, w310, ps0[mi * 2 + rh]));
                        ps1[mi * 2 + rh] = fmaf(v0, w301, fmaf(v1, w311, ps1[mi * 2 + rh]));
                    }
                }
            }
        }
        __syncthreads();
    }

    // ---- layer-3 reduction via shared atomics ----
    #pragma unroll
    for (int mi = 0; mi < 4; ++mi)
        #pragma unroll
        for (int rh = 0; rh < 2; ++rh) {
            int p = wm * 64 + mi * 16 + (lid >> 2) + rh * 8;
            atomicAdd(&par[PF_RED + p * 2 + 0], ps0[mi * 2 + rh]);
            atomicAdd(&par[PF_RED + p * 2 + 1], ps1[mi * 2 + rh]);
        }
    __syncthreads();

    if (wid < 4) {
        int p = wid * 32 + lid;
        float cc = par[PF_CS + p];
        float q0 = par[PF_YPX + p], q1 = par[PF_YPY + p];
        float s0 = par[PF_RED + p * 2 + 0];
        float s1 = par[PF_RED + p * 2 + 1];
        s0 += q0 * par[PF_W3 + 512] + q1 * par[PF_W3 + 514];
        s1 += q0 * par[PF_W3 + 513] + q1 * par[PF_W3 + 515];
        float v0 = s0 + par[PF_W3 + 516];
        float v1 = s1 + par[PF_W3 + 517];
        float g0 = sigmoidf_fast(cc * par[PF_W3 + 518] + par[PF_W3 + 520]);
        float g1 = sigmoidf_fast(cc * par[PF_W3 + 519] + par[PF_W3 + 521]);
        v0 = g0 * v0 + cc * par[PF_W3 + 522];
        v1 = g1 * v1 + cc * par[PF_W3 + 523];
        *(float2*)(out_g + ((size_t)b * NN + p0 + p) * 2) = make_float2(v0, v1);
    }
}

extern "C" void kernel_launch(void* const* d_in, const int* in_sizes, int n_in,
                              void* d_out, int out_size) {
    (void)in_sizes; (void)n_in; (void)out_size;
    const float* ctx = (const float*)d_in[0];
    const float* y   = (const float*)d_in[1];
    const float* yp  = (const float*)d_in[2];
    const float* tnw = (const float*)d_in[3];
    float* out = (float*)d_out;

    prep_weights_kernel<<<1024, 256>>>(tnw);

    cudaFuncSetAttribute(ode_hypernet_mma_kernel,
                         cudaFuncAttributeMaxDynamicSharedMemorySize, SMEM_TOTAL);
    dim3 grid(NN / TP, BB);
    ode_hypernet_mma_kernel<<<grid, 256, SMEM_TOTAL>>>(ctx, y, yp, tnw, out);
}

// round 6
// speedup vs baseline: 3.6558x; 1.3380x over previous
#include <cuda_runtime.h>
#include <cuda_bf16.h>
#include <cstdint>

typedef unsigned int u32;

// ---------------- problem constants ----------------
#define BB 64
#define NN 2048
#define TW 136716
#define TP 128

// ---------------- smem layout (bytes) ----------------
#define SM_AHI 0
#define SM_ALO 65536
#define SM_B   131072        // [2 buf][2 h][16384]
#define SM_PAR 196608
// float offsets inside PAR
#define PF_FILM  0
#define PF_WTAIL 1024
#define PF_W3    1536
#define PF_CS    2064
#define PF_YPX   2192
#define PF_YPY   2320
#define PF_YS    2448
#define PF_W0    2704
#define PF_RED   3728
#define SMEM_TOTAL (196608 + 3984*4)

// precomputed bf16 weights: [b][l][h][kc 8][swizzled 16KB chunk] = 32 MB
__device__ uint4 g_wbf[2097152];

// ---------------- helpers ----------------
__device__ __forceinline__ u32 smem_u32(const void* p) {
    u32 a; asm("{ .reg .u64 t; cvta.to.shared.u64 t, %1; cvt.u32.u64 %0, t; }" : "=r"(a) : "l"(p));
    return a;
}
__device__ __forceinline__ u32 pack_bf2(float a, float b) {
    __nv_bfloat162 t = __floats2bfloat162_rn(a, b);
    return *reinterpret_cast<u32*>(&t);
}
__device__ __forceinline__ void ldsm4(u32& r0, u32& r1, u32& r2, u32& r3, u32 addr) {
    asm volatile("ldmatrix.sync.aligned.m8n8.x4.shared.b16 {%0,%1,%2,%3}, [%4];"
                 : "=r"(r0), "=r"(r1), "=r"(r2), "=r"(r3) : "r"(addr));
}
__device__ __forceinline__ void mma16816(float& c0, float& c1, float& c2, float& c3,
                                         u32 a0, u32 a1, u32 a2, u32 a3,
                                         u32 b0, u32 b1) {
    asm volatile("mma.sync.aligned.m16n8k16.row.col.f32.bf16.bf16.f32 "
                 "{%0,%1,%2,%3}, {%4,%5,%6,%7}, {%8,%9}, {%0,%1,%2,%3};"
                 : "+f"(c0), "+f"(c1), "+f"(c2), "+f"(c3)
                 : "r"(a0), "r"(a1), "r"(a2), "r"(a3), "r"(b0), "r"(b1));
}
__device__ __forceinline__ void cpasync16(u32 dst, const void* src) {
    asm volatile("cp.async.cg.shared.global [%0], [%1], 16;" :: "r"(dst), "l"(src));
}
#define CP_COMMIT() asm volatile("cp.async.commit_group;" ::: "memory")
#define CP_WAIT0()  asm volatile("cp.async.wait_group 0;" ::: "memory")

__device__ __forceinline__ float ex2f(float x){ float r; asm("ex2.approx.ftz.f32 %0, %1;" : "=f"(r) : "f"(x)); return r; }
__device__ __forceinline__ float lg2f(float x){ float r; asm("lg2.approx.ftz.f32 %0, %1;" : "=f"(r) : "f"(x)); return r; }
__device__ __forceinline__ float rcpf(float x){ float r; asm("rcp.approx.ftz.f32 %0, %1;" : "=f"(r) : "f"(x)); return r; }
__device__ __forceinline__ float sigmoidf_fast(float x) {
    return rcpf(1.0f + ex2f(-1.4426950408889634f * x));
}
__device__ __forceinline__ float softplusf_fast(float x) {
    float e = ex2f(-1.4426950408889634f * fabsf(x));
    return fmaxf(x, 0.0f) + 0.6931471805599453f * lg2f(1.0f + e);
}

// A smem byte address: row-major 512B rows, 16B-unit XOR swizzle on bits 4-6
__device__ __forceinline__ u32 a_byte(int row, u32 kb) {
    return (u32)row * 512 + (kb ^ (((u32)row & 7) << 4));
}

// ---------------- prep kernel: f32 W -> bf16 hi/lo swizzled chunk images ----------------
__global__ __launch_bounds__(256)
void prep_weights_kernel(const float* __restrict__ tnw)
{
    __shared__ float s[32 * 257];
    int blkid = blockIdx.x;          // bl(0..127)*8 + ntile
    int nt = blkid & 7;
    int bl = blkid >> 3;
    int l = bl & 1;
    int b = bl >> 1;
    int n0 = nt * 32;
    const float* wl = tnw + (size_t)b * TW + (l == 0 ? 2048 : 69120);
    int t = threadIdx.x;

    int kq = t >> 5;
    int nq = t & 31;
    for (int kk = 0; kk < 256; kk += 8)
        s[nq * 257 + kk + kq] = wl[(size_t)(kk + kq) * 256 + n0 + nq];
    __syncthreads();

    int n = t & 31;
    int seg = t >> 5;
    int nG = n0 + n;
    u32 xr = (((u32)nG >> 1) & 3) << 4;
    char* gw = (char*)g_wbf;
    size_t base0 = (size_t)((b * 2 + l) * 2 + 0) * 131072 + (size_t)seg * 16384
                 + (size_t)(nG >> 1) * 128 + (size_t)(nG & 1) * 64;
    size_t base1 = base0 + 131072;
    #pragma unroll
    for (int u = 0; u < 4; ++u) {
        u32 hi[4], lo[4];
        #pragma unroll
        for (int j = 0; j < 4; ++j) {
            float v0 = s[n * 257 + seg * 32 + u * 8 + 2 * j];
            float v1 = s[n * 257 + seg * 32 + u * 8 + 2 * j + 1];
            float h0 = __bfloat162float(__float2bfloat16_rn(v0));
            float h1 = __bfloat162float(__float2bfloat16_rn(v1));
            hi[j] = pack_bf2(v0, v1);
            lo[j] = pack_bf2(v0 - h0, v1 - h1);
        }
        u32 off = ((u32)(u * 16)) ^ xr;
        *(uint4*)(gw + base0 + off) = make_uint4(hi[0], hi[1], hi[2], hi[3]);
        *(uint4*)(gw + base1 + off) = make_uint4(lo[0], lo[1], lo[2], lo[3]);
    }
}

// ---------------- main kernel: 512 threads, 16 warps (32x64 warp tiles) ----------------
__global__ __launch_bounds__(512, 1)
void ode_hypernet_mma_kernel(const float* __restrict__ ctx_g,
                             const float* __restrict__ y_g,
                             const float* __restrict__ yp_g,
                             const float* __restrict__ tnw_g,
                             float* __restrict__ out_g)
{
    extern __shared__ char smc[];
    float* par = (float*)(smc + SM_PAR);
    const u32 smb = smem_u32(smc);

    const int tid = threadIdx.x;
    const int lid = tid & 31;
    const int wid = tid >> 5;
    const int wm = wid & 3;          // m-quarter (32 rows)
    const int wn = wid >> 2;         // n-quarter (64 cols)
    const int b  = blockIdx.y;
    const int p0 = blockIdx.x * TP;
    const float* w = tnw_g + (size_t)b * TW;
    const char* gw = (const char*)g_wbf;
    const size_t gbase = (size_t)(b * 4) * 131072;   // [b][l][h] images

    // chunk prefetch: stream item g in 0..15 -> layer l=1+(g>>3), kc=g&7, buf=g&1
    auto load_chunk_g = [&](int g) {
        int kc = g & 7;
        size_t lb = gbase + (size_t)((g >> 3) * 2) * 131072 + (size_t)kc * 16384;
        u32 dbase = smb + SM_B + (u32)(g & 1) * 32768;
        u32 toff = (u32)tid * 16;
        cpasync16(dbase + toff,         gw + lb + toff);
        cpasync16(dbase + 8192 + toff,  gw + lb + 8192 + toff);
        cpasync16(dbase + 16384 + toff, gw + lb + 131072 + toff);
        cpasync16(dbase + 24576 + toff, gw + lb + 131072 + 8192 + toff);
        CP_COMMIT();
    };

    // ---- initial loads ----
    if (tid < 128) {
        par[PF_CS + tid] = ctx_g[(size_t)b * NN + p0 + tid];
        size_t base = ((size_t)b * NN + p0 + tid) * 2;
        par[PF_YPX + tid] = yp_g[base + 0];
        par[PF_YPY + tid] = yp_g[base + 1];
    }
    if (tid < 256) par[PF_YS + tid] = y_g[((size_t)b * NN + p0) * 2 + tid];
    par[PF_W0 + tid]         = w[tid];
    par[PF_W0 + 512 + tid]   = w[512 + tid];
    par[PF_FILM + tid]       = w[1024 + tid];
    par[PF_FILM + 512 + tid] = w[1536 + tid];
    if (tid < 524 - 512) par[PF_W3 + 512 + tid] = w[136192 + 512 + tid];
    par[PF_W3 + tid] = w[136192 + tid];

    // start streaming first B chunk while layer 0 computes
    load_chunk_g(0);
    __syncthreads();

    // ---- layer 0 (SIMT): 4 -> 256, FiLM + softplus, write A hi/lo ----
    {
        int p = tid & 127;
        int h2 = tid >> 7;           // 0..3, each covers 64 channels
        float y0 = par[PF_YS + 2 * p], y1 = par[PF_YS + 2 * p + 1];
        float q0 = par[PF_YPX + p],    q1 = par[PF_YPY + p];
        float cc = par[PF_CS + p];
        #pragma unroll 4
        for (int j = 0; j < 32; ++j) {
            int ch = h2 * 64 + 2 * j;
            float v0 = y0 * par[PF_W0 + ch]       + y1 * par[PF_W0 + 256 + ch]
                     + q0 * par[PF_W0 + 512 + ch] + q1 * par[PF_W0 + 768 + ch]
                     + par[PF_FILM + ch];
            float v1 = y0 * par[PF_W0 + ch + 1]       + y1 * par[PF_W0 + 256 + ch + 1]
                     + q0 * par[PF_W0 + 512 + ch + 1] + q1 * par[PF_W0 + 768 + ch + 1]
                     + par[PF_FILM + ch + 1];
            float s0 = sigmoidf_fast(cc * par[PF_FILM + 256 + ch]     + par[PF_FILM + 512 + ch]);
            float s1 = sigmoidf_fast(cc * par[PF_FILM + 256 + ch + 1] + par[PF_FILM + 512 + ch + 1]);
            v0 = s0 * v0 + cc * par[PF_FILM + 768 + ch];
            v1 = s1 * v1 + cc * par[PF_FILM + 768 + ch + 1];
            v0 = softplusf_fast(v0);
            v1 = softplusf_fast(v1);
            u32 byte = a_byte(p, (u32)(2 * ch));
            float h0 = __bfloat162float(__float2bfloat16_rn(v0));
            float h1 = __bfloat162float(__float2bfloat16_rn(v1));
            *(u32*)(smc + SM_AHI + byte) = pack_bf2(v0, v1);
            *(u32*)(smc + SM_ALO + byte) = pack_bf2(v0 - h0, v1 - h1);
        }
    }
    CP_WAIT0();
    __syncthreads();

    // ---- per-thread ldmatrix address constants ----
    u32 abase_[2], axor_[2];
    #pragma unroll
    for (int mi = 0; mi < 2; ++mi) {
        int arow = wm * 32 + mi * 16 + (lid & 15);
        abase_[mi] = (u32)arow * 512;
        axor_[mi]  = ((u32)arow & 7) << 4;
    }
    const u32 aksel = ((u32)(lid >> 4) & 1) << 4;
    u32 bbase_[4], bxor_[4];
    #pragma unroll
    for (int nt = 0; nt < 4; ++nt) {
        int brow = wn * 64 + nt * 16 + (lid & 7) + ((lid & 16) >> 1);
        bbase_[nt] = ((u32)(brow >> 1)) * 128 + ((u32)brow & 1) * 64;
        bxor_[nt]  = (((u32)brow >> 1) & 3) << 4;
    }
    const u32 bksel = ((u32)(lid >> 3) & 1) << 4;

    float ps0[4], ps1[4];   // fused layer-3 partials (mi x rh)

    #pragma unroll 1
    for (int l = 1; l <= 2; ++l) {
        const float* wl = w + ((l == 1) ? 2048 : 69120);
        const float* fp = wl + 66048;
        par[PF_FILM + tid]       = fp[tid];
        par[PF_FILM + 512 + tid] = fp[512 + tid];
        par[PF_WTAIL + tid]      = wl[65536 + tid];
        __syncthreads();

        float acc[2][8][4];
        #pragma unroll
        for (int mi = 0; mi < 2; ++mi)
            #pragma unroll
            for (int n8 = 0; n8 < 8; ++n8)
                #pragma unroll
                for (int q = 0; q < 4; ++q) acc[mi][n8][q] = 0.0f;

        #pragma unroll 1
        for (int kc = 0; kc < 8; ++kc) {
            int g = (l - 1) * 8 + kc;
            int buf = g & 1;
            if (g < 15) load_chunk_g(g + 1);

            u32 hb = smb + SM_B + (u32)buf * 32768;
            #pragma unroll
            for (int ks = 0; ks < 2; ++ks) {
                u32 kbA = (u32)(kc * 64 + ks * 32);
                u32 ah[2][4], al[2][4];
                #pragma unroll
                for (int mi = 0; mi < 2; ++mi) {
                    u32 off = abase_[mi] + ((kbA + aksel) ^ axor_[mi]);
                    ldsm4(ah[mi][0], ah[mi][1], ah[mi][2], ah[mi][3], smb + SM_AHI + off);
                    ldsm4(al[mi][0], al[mi][1], al[mi][2], al[mi][3], smb + SM_ALO + off);
                }
                #pragma unroll
                for (int nt = 0; nt < 4; ++nt) {
                    u32 bh[4], bl[4];
                    u32 off = bbase_[nt] + (((u32)(ks * 32) + bksel) ^ bxor_[nt]);
                    ldsm4(bh[0], bh[1], bh[2], bh[3], hb + off);
                    ldsm4(bl[0], bl[1], bl[2], bl[3], hb + 16384 + off);
                    #pragma unroll
                    for (int mi = 0; mi < 2; ++mi)
                        #pragma unroll
                        for (int p2 = 0; p2 < 2; ++p2) {
                            int n8 = nt * 2 + p2;
                            int pp = p2 * 2;
                            mma16816(acc[mi][n8][0], acc[mi][n8][1], acc[mi][n8][2], acc[mi][n8][3],
                                     ah[mi][0], ah[mi][1], ah[mi][2], ah[mi][3],
                                     bh[pp], bh[pp + 1]);
                            mma16816(acc[mi][n8][0], acc[mi][n8][1], acc[mi][n8][2], acc[mi][n8][3],
                                     ah[mi][0], ah[mi][1], ah[mi][2], ah[mi][3],
                                     bl[pp], bl[pp + 1]);
                            mma16816(acc[mi][n8][0], acc[mi][n8][1], acc[mi][n8][2], acc[mi][n8][3],
                                     al[mi][0], al[mi][1], al[mi][2], al[mi][3],
                                     bh[pp], bh[pp + 1]);
                        }
                }
            }
            CP_WAIT0();
            __syncthreads();
        }

        if (l == 2) {
            if (tid < 256) par[PF_RED + tid] = 0.0f;
            #pragma unroll
            for (int i = 0; i < 4; ++i) { ps0[i] = 0.0f; ps1[i] = 0.0f; }
            __syncthreads();
        }

        // ---- epilogue ----
        #pragma unroll
        for (int n8 = 0; n8 < 8; ++n8) {
            int col0 = wn * 64 + n8 * 8 + (lid & 3) * 2;
            int col1 = col0 + 1;
            float bi0  = par[PF_FILM + col0],       bi1  = par[PF_FILM + col1];
            float wsc0 = par[PF_FILM + 256 + col0], wsc1 = par[PF_FILM + 256 + col1];
            float bsc0 = par[PF_FILM + 512 + col0], bsc1 = par[PF_FILM + 512 + col1];
            float wsh0 = par[PF_FILM + 768 + col0], wsh1 = par[PF_FILM + 768 + col1];
            float wt00 = par[PF_WTAIL + col0],       wt01 = par[PF_WTAIL + col1];
            float wt10 = par[PF_WTAIL + 256 + col0], wt11 = par[PF_WTAIL + 256 + col1];
            float w300 = 0.f, w301 = 0.f, w310 = 0.f, w311 = 0.f;
            if (l == 2) {
                w300 = par[PF_W3 + 2 * col0];     w301 = par[PF_W3 + 2 * col0 + 1];
                w310 = par[PF_W3 + 2 * col1];     w311 = par[PF_W3 + 2 * col1 + 1];
            }
            #pragma unroll
            for (int mi = 0; mi < 2; ++mi) {
                #pragma unroll
                for (int rh = 0; rh < 2; ++rh) {
                    int row = wm * 32 + mi * 16 + (lid >> 2) + rh * 8;
                    float cc = par[PF_CS + row];
                    float q0 = par[PF_YPX + row], q1 = par[PF_YPY + row];
                    float v0 = acc[mi][n8][rh * 2 + 0];
                    float v1 = acc[mi][n8][rh * 2 + 1];
                    v0 += bi0 + q0 * wt00 + q1 * wt10;
                    v1 += bi1 + q0 * wt01 + q1 * wt11;
                    float s0 = sigmoidf_fast(cc * wsc0 + bsc0);
                    float s1 = sigmoidf_fast(cc * wsc1 + bsc1);
                    v0 = s0 * v0 + cc * wsh0;
                    v1 = s1 * v1 + cc * wsh1;
                    v0 = softplusf_fast(v0);
                    v1 = softplusf_fast(v1);
                    if (l == 1) {
                        u32 byte = a_byte(row, (u32)(2 * col0));
                        float h0 = __bfloat162float(__float2bfloat16_rn(v0));
                        float h1 = __bfloat162float(__float2bfloat16_rn(v1));
                        *(u32*)(smc + SM_AHI + byte) = pack_bf2(v0, v1);
                        *(u32*)(smc + SM_ALO + byte) = pack_bf2(v0 - h0, v1 - h1);
                    } else {
                        ps0[mi * 2 + rh] = fmaf(v0, w300, fmaf(v1, w310, ps0[mi * 2 + rh]));
                        ps1[mi * 2 + rh] = fmaf(v0, w301, fmaf(v1, w311, ps1[mi * 2 + rh]));
                    }
                }
            }
        }
        __syncthreads();
    }

    // ---- layer-3 reduction via shared atomics ----
    #pragma unroll
    for (int mi = 0; mi < 2; ++mi)
        #pragma unroll
        for (int rh = 0; rh < 2; ++rh) {
            int p = wm * 32 + mi * 16 + (lid >> 2) + rh * 8;
            atomicAdd(&par[PF_RED + p * 2 + 0], ps0[mi * 2 + rh]);
            atomicAdd(&par[PF_RED + p * 2 + 1], ps1[mi * 2 + rh]);
        }
    __syncthreads();

    if (wid < 4) {
        int p = wid * 32 + lid;
        float cc = par[PF_CS + p];
        float q0 = par[PF_YPX + p], q1 = par[PF_YPY + p];
        float s0 = par[PF_RED + p * 2 + 0];
        float s1 = par[PF_RED + p * 2 + 1];
        s0 += q0 * par[PF_W3 + 512] + q1 * par[PF_W3 + 514];
        s1 += q0 * par[PF_W3 + 513] + q1 * par[PF_W3 + 515];
        float v0 = s0 + par[PF_W3 + 516];
        float v1 = s1 + par[PF_W3 + 517];
        float g0 = sigmoidf_fast(cc * par[PF_W3 + 518] + par[PF_W3 + 520]);
        float g1 = sigmoidf_fast(cc * par[PF_W3 + 519] + par[PF_W3 + 521]);
        v0 = g0 * v0 + cc * par[PF_W3 + 522];
        v1 = g1 * v1 + cc * par[PF_W3 + 523];
        *(float2*)(out_g + ((size_t)b * NN + p0 + p) * 2) = make_float2(v0, v1);
    }
}

extern "C" void kernel_launch(void* const* d_in, const int* in_sizes, int n_in,
                              void* d_out, int out_size) {
    (void)in_sizes; (void)n_in; (void)out_size;
    const float* ctx = (const float*)d_in[0];
    const float* y   = (const float*)d_in[1];
    const float* yp  = (const float*)d_in[2];
    const float* tnw = (const float*)d_in[3];
    float* out = (float*)d_out;

    prep_weights_kernel<<<1024, 256>>>(tnw);

    cudaFuncSetAttribute(ode_hypernet_mma_kernel,
                         cudaFuncAttributeMaxDynamicSharedMemorySize, SMEM_TOTAL);
    dim3 grid(NN / TP, BB);
    ode_hypernet_mma_kernel<<<grid, 512, SMEM_TOTAL>>>(ctx, y, yp, tnw, out);
}

// round 7
// speedup vs baseline: 4.6018x; 1.2588x over previous
#include <cuda_runtime.h>
#include <cuda_fp16.h>
#include <cstdint>

typedef unsigned int u32;

// ---------------- problem constants ----------------
#define BB 64
#define NN 2048
#define TW 136716
#define TP 64

// ---------------- smem layout (bytes) ----------------
#define SM_A   0          // A fp16 frag-major: [4 m16][16 k16][32 lid][16B] = 32768
#define SM_B   32768      // 2 bufs x 32768 (each: [2 h][2 ks][16 n16][32 lid][16B])
#define SM_PAR 98304
// float offsets inside PAR
#define PF_FILM  0
#define PF_WTAIL 1024
#define PF_W3    1536
#define PF_CS    2064
#define PF_YPX   2128
#define PF_YPY   2192
#define PF_YS    2256
#define PF_W0    2384
#define PF_RED   3408
#define SMEM_TOTAL (98304 + 3536*4)   // 112448

#define BSCALE     1024.0f
#define INV_BSCALE 0.0009765625f

// precomputed fp16 weights, frag-major: [b][l][h][kc 8][4096 u32] = 32 MB
__device__ uint4 g_wbf[2097152];

// ---------------- helpers ----------------
__device__ __forceinline__ u32 smem_u32(const void* p) {
    u32 a; asm("{ .reg .u64 t; cvta.to.shared.u64 t, %1; cvt.u32.u64 %0, t; }" : "=r"(a) : "l"(p));
    return a;
}
__device__ __forceinline__ u32 pack_h2(float a, float b) {
    __half2 t = __floats2half2_rn(a, b);
    return *reinterpret_cast<u32*>(&t);
}
__device__ __forceinline__ void lds128(u32& r0, u32& r1, u32& r2, u32& r3, u32 addr) {
    asm volatile("ld.shared.v4.u32 {%0,%1,%2,%3}, [%4];"
                 : "=r"(r0), "=r"(r1), "=r"(r2), "=r"(r3) : "r"(addr));
}
__device__ __forceinline__ void mmaf16(float& c0, float& c1, float& c2, float& c3,
                                       u32 a0, u32 a1, u32 a2, u32 a3,
                                       u32 b0, u32 b1) {
    asm volatile("mma.sync.aligned.m16n8k16.row.col.f32.f16.f16.f32 "
                 "{%0,%1,%2,%3}, {%4,%5,%6,%7}, {%8,%9}, {%0,%1,%2,%3};"
                 : "+f"(c0), "+f"(c1), "+f"(c2), "+f"(c3)
                 : "r"(a0), "r"(a1), "r"(a2), "r"(a3), "r"(b0), "r"(b1));
}
__device__ __forceinline__ void cpasync16(u32 dst, const void* src) {
    asm volatile("cp.async.cg.shared.global [%0], [%1], 16;" :: "r"(dst), "l"(src));
}
#define CP_COMMIT() asm volatile("cp.async.commit_group;" ::: "memory")
#define CP_WAIT0()  asm volatile("cp.async.wait_group 0;" ::: "memory")

__device__ __forceinline__ float ex2f(float x){ float r; asm("ex2.approx.ftz.f32 %0, %1;" : "=f"(r) : "f"(x)); return r; }
__device__ __forceinline__ float lg2f(float x){ float r; asm("lg2.approx.ftz.f32 %0, %1;" : "=f"(r) : "f"(x)); return r; }
__device__ __forceinline__ float rcpf(float x){ float r; asm("rcp.approx.ftz.f32 %0, %1;" : "=f"(r) : "f"(x)); return r; }
__device__ __forceinline__ float sigmoidf_fast(float x) {
    return rcpf(1.0f + ex2f(-1.4426950408889634f * x));
}
__device__ __forceinline__ float softplusf_fast(float x) {
    float e = ex2f(-1.4426950408889634f * fabsf(x));
    return fmaxf(x, 0.0f) + 0.6931471805599453f * lg2f(1.0f + e);
}

// ---------------- prep: f32 W -> fp16 hi/lo (x1024) frag-major images ----------------
// B-frag reg layout per (kc chunk 32ch): linear u32 idx = ((ks*16+n16)*32+lid)*4+reg
//   reg bit0 = k-half (+8), bit1 = n-half (+8); koff=2(lid&3), noff=lid>>2
__global__ __launch_bounds__(256)
void prep_weights_kernel(const float* __restrict__ tnw)
{
    __shared__ float s[32][257];
    int bl = blockIdx.x;           // 0..127
    int l = bl & 1, b = bl >> 1;
    const float* wl = tnw + (size_t)b * TW + (l == 0 ? 2048 : 69120);
    int t = threadIdx.x;
    u32* gh = (u32*)g_wbf;

    for (int kc = 0; kc < 8; ++kc) {
        __syncthreads();
        #pragma unroll
        for (int j = 0; j < 32; ++j) {
            int idx = t + j * 256;               // 8192 floats
            int r = idx >> 8, c = idx & 255;
            s[r][c] = wl[(size_t)(kc * 32 + r) * 256 + c];
        }
        __syncthreads();
        size_t base0 = ((size_t)((b * 2 + l) * 2 + 0) * 8 + kc) * 4096;
        size_t base1 = ((size_t)((b * 2 + l) * 2 + 1) * 8 + kc) * 4096;
        #pragma unroll
        for (int j = 0; j < 16; ++j) {
            int idx = t + j * 256;               // 0..4095
            int reg = idx & 3;
            int lid = (idx >> 2) & 31;
            int n16 = (idx >> 7) & 15;
            int ks  = idx >> 11;
            int koff = ks * 16 + 2 * (lid & 3) + 8 * (reg & 1);
            int n = n16 * 16 + (lid >> 2) + 8 * (reg >> 1);
            float w0 = s[koff][n] * BSCALE;
            float w1 = s[koff + 1][n] * BSCALE;
            __half h0 = __float2half_rn(w0);
            __half h1 = __float2half_rn(w1);
            __half l0 = __float2half_rn(w0 - __half2float(h0));
            __half l1 = __float2half_rn(w1 - __half2float(h1));
            __half2 ph = __halves2half2(h0, h1);
            __half2 pl = __halves2half2(l0, l1);
            gh[base0 + idx] = *reinterpret_cast<u32*>(&ph);
            gh[base1 + idx] = *reinterpret_cast<u32*>(&pl);
        }
    }
}

// ---------------- main kernel: 256 threads, 8 warps (64x32 warp tiles), 2 CTAs/SM ----------------
__global__ __launch_bounds__(256, 2)
void ode_hypernet_mma_kernel(const float* __restrict__ ctx_g,
                             const float* __restrict__ y_g,
                             const float* __restrict__ yp_g,
                             const float* __restrict__ tnw_g,
                             float* __restrict__ out_g)
{
    extern __shared__ char smc[];
    float* par = (float*)(smc + SM_PAR);
    const u32 smb = smem_u32(smc);

    const int tid = threadIdx.x;
    const int lid = tid & 31;
    const int wid = tid >> 5;        // = wn, 8 warps x 32 cols
    const int b  = blockIdx.y;
    const int p0 = blockIdx.x * TP;
    const float* w = tnw_g + (size_t)b * TW;
    const char* gw = (const char*)g_wbf;

    // chunk stream: g 0..15 -> layer (g>>3), kc (g&7), buf (g&1); 32KB per chunk (hi+lo)
    auto load_chunk_g = [&](int g) {
        size_t h0 = ((size_t)((b * 2 + (g >> 3)) * 2 + 0) * 8 + (g & 7)) * 16384;
        size_t h1 = ((size_t)((b * 2 + (g >> 3)) * 2 + 1) * 8 + (g & 7)) * 16384;
        u32 dbase = smb + SM_B + (u32)(g & 1) * 32768;
        #pragma unroll
        for (int i = 0; i < 4; ++i) {
            u32 off = (u32)(tid + i * 256) * 16;
            cpasync16(dbase + off,         gw + h0 + off);
            cpasync16(dbase + 16384 + off, gw + h1 + off);
        }
        CP_COMMIT();
    };

    // ---- initial loads ----
    if (tid < 64) {
        par[PF_CS + tid] = ctx_g[(size_t)b * NN + p0 + tid];
        size_t base = ((size_t)b * NN + p0 + tid) * 2;
        par[PF_YPX + tid] = yp_g[base + 0];
        par[PF_YPY + tid] = yp_g[base + 1];
    }
    if (tid < 128) par[PF_YS + tid] = y_g[((size_t)b * NN + p0) * 2 + tid];
    #pragma unroll
    for (int i = 0; i < 4; ++i) par[PF_W0 + i * 256 + tid] = w[i * 256 + tid];
    #pragma unroll
    for (int i = 0; i < 4; ++i) par[PF_FILM + i * 256 + tid] = w[1024 + i * 256 + tid];
    for (int i = tid; i < 524; i += 256) par[PF_W3 + i] = w[136192 + i];

    load_chunk_g(0);
    __syncthreads();

    // ---- layer 0 (SIMT): 4 -> 256, FiLM + softplus, write A fp16 frag-major ----
    {
        int p = tid & 63;
        int h2 = tid >> 6;           // 0..3, 64 channels each
        float y0 = par[PF_YS + 2 * p], y1 = par[PF_YS + 2 * p + 1];
        float q0 = par[PF_YPX + p],    q1 = par[PF_YPY + p];
        float cc = par[PF_CS + p];
        int m16 = p >> 4;
        int plid4 = (p & 7) * 4;
        int preg = (p >> 3) & 1;
        #pragma unroll 4
        for (int j = 0; j < 32; ++j) {
            int ch = h2 * 64 + 2 * j;
            float v0 = y0 * par[PF_W0 + ch]       + y1 * par[PF_W0 + 256 + ch]
                     + q0 * par[PF_W0 + 512 + ch] + q1 * par[PF_W0 + 768 + ch]
                     + par[PF_FILM + ch];
            float v1 = y0 * par[PF_W0 + ch + 1]       + y1 * par[PF_W0 + 256 + ch + 1]
                     + q0 * par[PF_W0 + 512 + ch + 1] + q1 * par[PF_W0 + 768 + ch + 1]
                     + par[PF_FILM + ch + 1];
            float s0 = sigmoidf_fast(cc * par[PF_FILM + 256 + ch]     + par[PF_FILM + 512 + ch]);
            float s1 = sigmoidf_fast(cc * par[PF_FILM + 256 + ch + 1] + par[PF_FILM + 512 + ch + 1]);
            v0 = s0 * v0 + cc * par[PF_FILM + 768 + ch];
            v1 = s1 * v1 + cc * par[PF_FILM + 768 + ch + 1];
            v0 = softplusf_fast(v0);
            v1 = softplusf_fast(v1);
            int k16 = ch >> 4;
            int flid = plid4 + (j & 3);
            int reg  = preg + 2 * ((j >> 2) & 1);
            u32 off = (u32)((m16 * 16 + k16) * 32 + flid) * 16 + (u32)reg * 4;
            *(u32*)(smc + SM_A + off) = pack_h2(v0, v1);
        }
    }
    CP_WAIT0();
    __syncthreads();

    float ps0[8], ps1[8];            // layer-3 partials (mi x rh)

    #pragma unroll 1
    for (int l = 1; l <= 2; ++l) {
        const float* wl = w + ((l == 1) ? 2048 : 69120);
        const float* fp = wl + 66048;
        #pragma unroll
        for (int i = 0; i < 4; ++i) par[PF_FILM + i * 256 + tid] = fp[i * 256 + tid];
        par[PF_WTAIL + tid]       = wl[65536 + tid];
        par[PF_WTAIL + 256 + tid] = wl[65792 + tid];

        float acc[4][4][4];
        #pragma unroll
        for (int mi = 0; mi < 4; ++mi)
            #pragma unroll
            for (int n8 = 0; n8 < 4; ++n8)
                #pragma unroll
                for (int q = 0; q < 4; ++q) acc[mi][n8][q] = 0.0f;

        #pragma unroll 1
        for (int kc = 0; kc < 8; ++kc) {
            int g = (l - 1) * 8 + kc;
            int buf = g & 1;
            if (g < 15) load_chunk_g(g + 1);

            u32 bbuf = smb + SM_B + (u32)buf * 32768;
            #pragma unroll
            for (int ks = 0; ks < 2; ++ks) {
                int k16 = kc * 2 + ks;
                // A frags: 4 x LDS.128 (fp16, frag-major)
                u32 a[4][4];
                #pragma unroll
                for (int mi = 0; mi < 4; ++mi)
                    lds128(a[mi][0], a[mi][1], a[mi][2], a[mi][3],
                           smb + SM_A + (u32)((mi * 16 + k16) * 32 + lid) * 16);
                // B frags: hi/lo x 2 n16-groups
                u32 bh[2][4], bl[2][4];
                #pragma unroll
                for (int nt = 0; nt < 2; ++nt) {
                    u32 off = (u32)((ks * 16 + wid * 2 + nt) * 32 + lid) * 16;
                    lds128(bh[nt][0], bh[nt][1], bh[nt][2], bh[nt][3], bbuf + off);
                    lds128(bl[nt][0], bl[nt][1], bl[nt][2], bl[nt][3], bbuf + 16384 + off);
                }
                // term 1: A x Bhi (16 independent chains)
                #pragma unroll
                for (int mi = 0; mi < 4; ++mi)
                    #pragma unroll
                    for (int n8 = 0; n8 < 4; ++n8) {
                        int nt = n8 >> 1, pp = (n8 & 1) * 2;
                        mmaf16(acc[mi][n8][0], acc[mi][n8][1], acc[mi][n8][2], acc[mi][n8][3],
                               a[mi][0], a[mi][1], a[mi][2], a[mi][3],
                               bh[nt][pp], bh[nt][pp + 1]);
                    }
                // term 2: A x Blo
                #pragma unroll
                for (int mi = 0; mi < 4; ++mi)
                    #pragma unroll
                    for (int n8 = 0; n8 < 4; ++n8) {
                        int nt = n8 >> 1, pp = (n8 & 1) * 2;
                        mmaf16(acc[mi][n8][0], acc[mi][n8][1], acc[mi][n8][2], acc[mi][n8][3],
                               a[mi][0], a[mi][1], a[mi][2], a[mi][3],
                               bl[nt][pp], bl[nt][pp + 1]);
                    }
            }
            CP_WAIT0();
            __syncthreads();
        }

        if (l == 2) {
            if (tid < 128) par[PF_RED + tid] = 0.0f;
            #pragma unroll
            for (int i = 0; i < 8; ++i) { ps0[i] = 0.0f; ps1[i] = 0.0f; }
            __syncthreads();
        }

        // ---- epilogue: FiLM + softplus ----
        #pragma unroll
        for (int n8 = 0; n8 < 4; ++n8) {
            int col0 = wid * 32 + n8 * 8 + (lid & 3) * 2;
            int col1 = col0 + 1;
            float bi0  = par[PF_FILM + col0],       bi1  = par[PF_FILM + col1];
            float wsc0 = par[PF_FILM + 256 + col0], wsc1 = par[PF_FILM + 256 + col1];
            float bsc0 = par[PF_FILM + 512 + col0], bsc1 = par[PF_FILM + 512 + col1];
            float wsh0 = par[PF_FILM + 768 + col0], wsh1 = par[PF_FILM + 768 + col1];
            float wt00 = par[PF_WTAIL + col0],       wt01 = par[PF_WTAIL + col1];
            float wt10 = par[PF_WTAIL + 256 + col0], wt11 = par[PF_WTAIL + 256 + col1];
            float w300 = 0.f, w301 = 0.f, w310 = 0.f, w311 = 0.f;
            if (l == 2) {
                w300 = par[PF_W3 + 2 * col0];     w301 = par[PF_W3 + 2 * col0 + 1];
                w310 = par[PF_W3 + 2 * col1];     w311 = par[PF_W3 + 2 * col1 + 1];
            }
            int k16n = wid * 2 + (n8 >> 1);     // next-layer k16 of this col pair
            #pragma unroll
            for (int mi = 0; mi < 4; ++mi) {
                #pragma unroll
                for (int rh = 0; rh < 2; ++rh) {
                    int row = mi * 16 + (lid >> 2) + rh * 8;
                    float cc = par[PF_CS + row];
                    float q0 = par[PF_YPX + row], q1 = par[PF_YPY + row];
                    float v0 = acc[mi][n8][rh * 2 + 0] * INV_BSCALE;
                    float v1 = acc[mi][n8][rh * 2 + 1] * INV_BSCALE;
                    v0 += bi0 + q0 * wt00 + q1 * wt10;
                    v1 += bi1 + q0 * wt01 + q1 * wt11;
                    float s0 = sigmoidf_fast(cc * wsc0 + bsc0);
                    float s1 = sigmoidf_fast(cc * wsc1 + bsc1);
                    v0 = s0 * v0 + cc * wsh0;
                    v1 = s1 * v1 + cc * wsh1;
                    v0 = softplusf_fast(v0);
                    v1 = softplusf_fast(v1);
                    if (l == 1) {
                        u32 off = (u32)((mi * 16 + k16n) * 32 + lid) * 16
                                + (u32)(rh + 2 * (n8 & 1)) * 4;
                        *(u32*)(smc + SM_A + off) = pack_h2(v0, v1);
                    } else {
                        ps0[mi * 2 + rh] = fmaf(v0, w300, fmaf(v1, w310, ps0[mi * 2 + rh]));
                        ps1[mi * 2 + rh] = fmaf(v0, w301, fmaf(v1, w311, ps1[mi * 2 + rh]));
                    }
                }
            }
        }
        __syncthreads();
    }

    // ---- layer-3 reduction via shared atomics ----
    #pragma unroll
    for (int mi = 0; mi < 4; ++mi)
        #pragma unroll
        for (int rh = 0; rh < 2; ++rh) {
            int p = mi * 16 + (lid >> 2) + rh * 8;
            atomicAdd(&par[PF_RED + p * 2 + 0], ps0[mi * 2 + rh]);
            atomicAdd(&par[PF_RED + p * 2 + 1], ps1[mi * 2 + rh]);
        }
    __syncthreads();

    if (tid < 128) {
        int p = tid >> 1;
        int o = tid & 1;
        float cc = par[PF_CS + p];
        float q0 = par[PF_YPX + p], q1 = par[PF_YPY + p];
        float s = par[PF_RED + p * 2 + o];
        s += q0 * par[PF_W3 + 512 + o] + q1 * par[PF_W3 + 514 + o];
        float v = s + par[PF_W3 + 516 + o];
        float g = sigmoidf_fast(cc * par[PF_W3 + 518 + o] + par[PF_W3 + 520 + o]);
        v = g * v + cc * par[PF_W3 + 522 + o];
        out_g[((size_t)b * NN + p0 + p) * 2 + o] = v;
    }
}

extern "C" void kernel_launch(void* const* d_in, const int* in_sizes, int n_in,
                              void* d_out, int out_size) {
    (void)in_sizes; (void)n_in; (void)out_size;
    const float* ctx = (const float*)d_in[0];
    const float* y   = (const float*)d_in[1];
    const float* yp  = (const float*)d_in[2];
    const float* tnw = (const float*)d_in[3];
    float* out = (float*)d_out;

    prep_weights_kernel<<<128, 256>>>(tnw);

    cudaFuncSetAttribute(ode_hypernet_mma_kernel,
                         cudaFuncAttributeMaxDynamicSharedMemorySize, SMEM_TOTAL);
    dim3 grid(NN / TP, BB);   // (32, 64)
    ode_hypernet_mma_kernel<<<grid, 256, SMEM_TOTAL>>>(ctx, y, yp, tnw, out);
}

// round 8
// speedup vs baseline: 5.9628x; 1.2957x over previous
#include <cuda_runtime.h>
#include <cuda_fp16.h>
#include <cstdint>

typedef unsigned int u32;

// ---------------- problem constants ----------------
#define BB 64
#define NN 2048
#define TW 136716
#define TP 64

// ---------------- smem layout (bytes) ----------------
#define SM_A   0          // A fp16 frag-major: [4 m16][16 k16][32 lid][16B] = 32768
#define SM_B   32768      // 2 bufs x 32768; each buf = 2 kc chunks of 16KB
#define SM_PAR 98304
// float offsets inside PAR
#define PF_FILM  0
#define PF_WTAIL 1024
#define PF_W3    1536
#define PF_CS    2064
#define PF_YPX   2128
#define PF_YPY   2192
#define PF_YS    2256
#define PF_W0    2384
#define PF_RED   3408
#define SMEM_TOTAL (98304 + 3536*4)   // 112448

#define BSCALE     1024.0f
#define INV_BSCALE 0.0009765625f

// precomputed fp16 weights, frag-major: [b][l][kc 8][4096 u32] = 16 MB used
__device__ uint4 g_wbf[2097152];

// ---------------- helpers ----------------
__device__ __forceinline__ u32 smem_u32(const void* p) {
    u32 a; asm("{ .reg .u64 t; cvta.to.shared.u64 t, %1; cvt.u32.u64 %0, t; }" : "=r"(a) : "l"(p));
    return a;
}
__device__ __forceinline__ u32 pack_h2(float a, float b) {
    __half2 t = __floats2half2_rn(a, b);
    return *reinterpret_cast<u32*>(&t);
}
__device__ __forceinline__ void lds128(u32& r0, u32& r1, u32& r2, u32& r3, u32 addr) {
    asm volatile("ld.shared.v4.u32 {%0,%1,%2,%3}, [%4];"
                 : "=r"(r0), "=r"(r1), "=r"(r2), "=r"(r3) : "r"(addr));
}
__device__ __forceinline__ void mmaf16(float& c0, float& c1, float& c2, float& c3,
                                       u32 a0, u32 a1, u32 a2, u32 a3,
                                       u32 b0, u32 b1) {
    asm volatile("mma.sync.aligned.m16n8k16.row.col.f32.f16.f16.f32 "
                 "{%0,%1,%2,%3}, {%4,%5,%6,%7}, {%8,%9}, {%0,%1,%2,%3};"
                 : "+f"(c0), "+f"(c1), "+f"(c2), "+f"(c3)
                 : "r"(a0), "r"(a1), "r"(a2), "r"(a3), "r"(b0), "r"(b1));
}
__device__ __forceinline__ void cpasync16(u32 dst, const void* src) {
    asm volatile("cp.async.cg.shared.global [%0], [%1], 16;" :: "r"(dst), "l"(src));
}
#define CP_COMMIT() asm volatile("cp.async.commit_group;" ::: "memory")
#define CP_WAIT0()  asm volatile("cp.async.wait_group 0;" ::: "memory")

__device__ __forceinline__ float ex2f(float x){ float r; asm("ex2.approx.ftz.f32 %0, %1;" : "=f"(r) : "f"(x)); return r; }
__device__ __forceinline__ float lg2f(float x){ float r; asm("lg2.approx.ftz.f32 %0, %1;" : "=f"(r) : "f"(x)); return r; }
__device__ __forceinline__ float rcpf(float x){ float r; asm("rcp.approx.ftz.f32 %0, %1;" : "=f"(r) : "f"(x)); return r; }
__device__ __forceinline__ float sigmoidf_fast(float x) {
    return rcpf(1.0f + ex2f(-1.4426950408889634f * x));
}
__device__ __forceinline__ float softplusf_fast(float x) {
    float e = ex2f(-1.4426950408889634f * fabsf(x));
    return fmaxf(x, 0.0f) + 0.6931471805599453f * lg2f(1.0f + e);
}

// ---------------- prep: f32 W -> fp16 (x1024) frag-major image ----------------
// per kc chunk (32 k-ch): linear u32 idx = ((ks*16+n16)*32+lid)*4+reg
//   reg bit0 = k-half (+8), bit1 = n-half (+8); koff=2(lid&3), noff=lid>>2
__global__ __launch_bounds__(256)
void prep_weights_kernel(const float* __restrict__ tnw)
{
    __shared__ float s[32][257];
    int bl = blockIdx.x;           // 0..127
    int l = bl & 1, b = bl >> 1;
    const float* wl = tnw + (size_t)b * TW + (l == 0 ? 2048 : 69120);
    int t = threadIdx.x;
    u32* gh = (u32*)g_wbf;

    for (int kc = 0; kc < 8; ++kc) {
        __syncthreads();
        #pragma unroll
        for (int j = 0; j < 32; ++j) {
            int idx = t + j * 256;               // 8192 floats
            int r = idx >> 8, c = idx & 255;
            s[r][c] = wl[(size_t)(kc * 32 + r) * 256 + c];
        }
        __syncthreads();
        size_t base0 = ((size_t)(b * 2 + l) * 8 + kc) * 4096;
        #pragma unroll
        for (int j = 0; j < 16; ++j) {
            int idx = t + j * 256;               // 0..4095
            int reg = idx & 3;
            int lid = (idx >> 2) & 31;
            int n16 = (idx >> 7) & 15;
            int ks  = idx >> 11;
            int koff = ks * 16 + 2 * (lid & 3) + 8 * (reg & 1);
            int n = n16 * 16 + (lid >> 2) + 8 * (reg >> 1);
            gh[base0 + idx] = pack_h2(s[koff][n] * BSCALE, s[koff + 1][n] * BSCALE);
        }
    }
}

// ---------------- main kernel: 256 threads, 8 warps (64x32 warp tiles), 2 CTAs/SM ----------------
__global__ __launch_bounds__(256, 2)
void ode_hypernet_mma_kernel(const float* __restrict__ ctx_g,
                             const float* __restrict__ y_g,
                             const float* __restrict__ yp_g,
                             const float* __restrict__ tnw_g,
                             float* __restrict__ out_g)
{
    extern __shared__ char smc[];
    float* par = (float*)(smc + SM_PAR);
    const u32 smb = smem_u32(smc);

    const int tid = threadIdx.x;
    const int lid = tid & 31;
    const int wid = tid >> 5;        // = wn, 8 warps x 32 cols
    const int b  = blockIdx.y;
    const int p0 = blockIdx.x * TP;
    const float* w = tnw_g + (size_t)b * TW;
    const char* gw = (const char*)g_wbf;

    // item stream: g 0..7 -> layer (g>>2), kc-pair (g&3), buf (g&1); 32KB per item
    auto load_chunk_g = [&](int g) {
        size_t src = ((size_t)(b * 2 + (g >> 2)) * 8 + (size_t)(g & 3) * 2) * 16384;
        u32 dbase = smb + SM_B + (u32)(g & 1) * 32768;
        #pragma unroll
        for (int i = 0; i < 8; ++i) {
            u32 off = (u32)(tid + i * 256) * 16;
            cpasync16(dbase + off, gw + src + off);
        }
        CP_COMMIT();
    };

    // ---- initial loads ----
    if (tid < 64) {
        par[PF_CS + tid] = ctx_g[(size_t)b * NN + p0 + tid];
        size_t base = ((size_t)b * NN + p0 + tid) * 2;
        par[PF_YPX + tid] = yp_g[base + 0];
        par[PF_YPY + tid] = yp_g[base + 1];
    }
    if (tid < 128) par[PF_YS + tid] = y_g[((size_t)b * NN + p0) * 2 + tid];
    #pragma unroll
    for (int i = 0; i < 4; ++i) par[PF_W0 + i * 256 + tid] = w[i * 256 + tid];
    #pragma unroll
    for (int i = 0; i < 4; ++i) par[PF_FILM + i * 256 + tid] = w[1024 + i * 256 + tid];
    for (int i = tid; i < 524; i += 256) par[PF_W3 + i] = w[136192 + i];

    load_chunk_g(0);
    __syncthreads();

    // ---- layer 0 (SIMT): 4 -> 256, FiLM + softplus, write A fp16 frag-major ----
    {
        int p = tid & 63;
        int h2 = tid >> 6;           // 0..3, 64 channels each
        float y0 = par[PF_YS + 2 * p], y1 = par[PF_YS + 2 * p + 1];
        float q0 = par[PF_YPX + p],    q1 = par[PF_YPY + p];
        float cc = par[PF_CS + p];
        int m16 = p >> 4;
        int plid4 = (p & 7) * 4;
        int preg = (p >> 3) & 1;
        #pragma unroll 4
        for (int j = 0; j < 32; ++j) {
            int ch = h2 * 64 + 2 * j;
            float v0 = y0 * par[PF_W0 + ch]       + y1 * par[PF_W0 + 256 + ch]
                     + q0 * par[PF_W0 + 512 + ch] + q1 * par[PF_W0 + 768 + ch]
                     + par[PF_FILM + ch];
            float v1 = y0 * par[PF_W0 + ch + 1]       + y1 * par[PF_W0 + 256 + ch + 1]
                     + q0 * par[PF_W0 + 512 + ch + 1] + q1 * par[PF_W0 + 768 + ch + 1]
                     + par[PF_FILM + ch + 1];
            float s0 = sigmoidf_fast(cc * par[PF_FILM + 256 + ch]     + par[PF_FILM + 512 + ch]);
            float s1 = sigmoidf_fast(cc * par[PF_FILM + 256 + ch + 1] + par[PF_FILM + 512 + ch + 1]);
            v0 = s0 * v0 + cc * par[PF_FILM + 768 + ch];
            v1 = s1 * v1 + cc * par[PF_FILM + 768 + ch + 1];
            v0 = softplusf_fast(v0);
            v1 = softplusf_fast(v1);
            int k16 = ch >> 4;
            int flid = plid4 + (j & 3);
            int reg  = preg + 2 * ((j >> 2) & 1);
            u32 off = (u32)((m16 * 16 + k16) * 32 + flid) * 16 + (u32)reg * 4;
            *(u32*)(smc + SM_A + off) = pack_h2(v0, v1);
        }
    }
    CP_WAIT0();
    __syncthreads();

    float ps0[8], ps1[8];            // layer-3 partials (mi x rh)

    #pragma unroll 1
    for (int l = 1; l <= 2; ++l) {
        const float* wl = w + ((l == 1) ? 2048 : 69120);
        const float* fp = wl + 66048;
        #pragma unroll
        for (int i = 0; i < 4; ++i) par[PF_FILM + i * 256 + tid] = fp[i * 256 + tid];
        par[PF_WTAIL + tid]       = wl[65536 + tid];
        par[PF_WTAIL + 256 + tid] = wl[65792 + tid];

        float acc[4][4][4];
        #pragma unroll
        for (int mi = 0; mi < 4; ++mi)
            #pragma unroll
            for (int n8 = 0; n8 < 4; ++n8)
                #pragma unroll
                for (int q = 0; q < 4; ++q) acc[mi][n8][q] = 0.0f;

        #pragma unroll 1
        for (int item = 0; item < 4; ++item) {
            int g = (l - 1) * 4 + item;
            int buf = g & 1;
            if (g < 7) load_chunk_g(g + 1);

            u32 bbuf = smb + SM_B + (u32)buf * 32768;
            #pragma unroll
            for (int kc2 = 0; kc2 < 2; ++kc2) {
                #pragma unroll
                for (int ks = 0; ks < 2; ++ks) {
                    int k16 = item * 4 + kc2 * 2 + ks;
                    // A frags: 4 x LDS.128 (fp16, frag-major)
                    u32 a[4][4];
                    #pragma unroll
                    for (int mi = 0; mi < 4; ++mi)
                        lds128(a[mi][0], a[mi][1], a[mi][2], a[mi][3],
                               smb + SM_A + (u32)((mi * 16 + k16) * 32 + lid) * 16);
                    // B frags: 2 n16-groups
                    u32 bh[2][4];
                    #pragma unroll
                    for (int nt = 0; nt < 2; ++nt) {
                        u32 off = (u32)kc2 * 16384
                                + (u32)((ks * 16 + wid * 2 + nt) * 32 + lid) * 16;
                        lds128(bh[nt][0], bh[nt][1], bh[nt][2], bh[nt][3], bbuf + off);
                    }
                    #pragma unroll
                    for (int mi = 0; mi < 4; ++mi)
                        #pragma unroll
                        for (int n8 = 0; n8 < 4; ++n8) {
                            int nt = n8 >> 1, pp = (n8 & 1) * 2;
                            mmaf16(acc[mi][n8][0], acc[mi][n8][1], acc[mi][n8][2], acc[mi][n8][3],
                                   a[mi][0], a[mi][1], a[mi][2], a[mi][3],
                                   bh[nt][pp], bh[nt][pp + 1]);
                        }
                }
            }
            CP_WAIT0();
            __syncthreads();
        }

        if (l == 2) {
            if (tid < 128) par[PF_RED + tid] = 0.0f;
            #pragma unroll
            for (int i = 0; i < 8; ++i) { ps0[i] = 0.0f; ps1[i] = 0.0f; }
            __syncthreads();
        }

        // ---- epilogue: FiLM + softplus ----
        #pragma unroll
        for (int n8 = 0; n8 < 4; ++n8) {
            int col0 = wid * 32 + n8 * 8 + (lid & 3) * 2;
            int col1 = col0 + 1;
            float bi0  = par[PF_FILM + col0],       bi1  = par[PF_FILM + col1];
            float wsc0 = par[PF_FILM + 256 + col0], wsc1 = par[PF_FILM + 256 + col1];
            float bsc0 = par[PF_FILM + 512 + col0], bsc1 = par[PF_FILM + 512 + col1];
            float wsh0 = par[PF_FILM + 768 + col0], wsh1 = par[PF_FILM + 768 + col1];
            float wt00 = par[PF_WTAIL + col0],       wt01 = par[PF_WTAIL + col1];
            float wt10 = par[PF_WTAIL + 256 + col0], wt11 = par[PF_WTAIL + 256 + col1];
            float w300 = 0.f, w301 = 0.f, w310 = 0.f, w311 = 0.f;
            if (l == 2) {
                w300 = par[PF_W3 + 2 * col0];     w301 = par[PF_W3 + 2 * col0 + 1];
                w310 = par[PF_W3 + 2 * col1];     w311 = par[PF_W3 + 2 * col1 + 1];
            }
            int k16n = wid * 2 + (n8 >> 1);     // next-layer k16 of this col pair
            #pragma unroll
            for (int mi = 0; mi < 4; ++mi) {
                #pragma unroll
                for (int rh = 0; rh < 2; ++rh) {
                    int row = mi * 16 + (lid >> 2) + rh * 8;
                    float cc = par[PF_CS + row];
                    float q0 = par[PF_YPX + row], q1 = par[PF_YPY + row];
                    float v0 = acc[mi][n8][rh * 2 + 0] * INV_BSCALE;
                    float v1 = acc[mi][n8][rh * 2 + 1] * INV_BSCALE;
                    v0 += bi0 + q0 * wt00 + q1 * wt10;
                    v1 += bi1 + q0 * wt01 + q1 * wt11;
                    float s0 = sigmoidf_fast(cc * wsc0 + bsc0);
                    float s1 = sigmoidf_fast(cc * wsc1 + bsc1);
                    v0 = s0 * v0 + cc * wsh0;
                    v1 = s1 * v1 + cc * wsh1;
                    v0 = softplusf_fast(v0);
                    v1 = softplusf_fast(v1);
                    if (l == 1) {
                        u32 off = (u32)((mi * 16 + k16n) * 32 + lid) * 16
                                + (u32)(rh + 2 * (n8 & 1)) * 4;
                        *(u32*)(smc + SM_A + off) = pack_h2(v0, v1);
                    } else {
                        ps0[mi * 2 + rh] = fmaf(v0, w300, fmaf(v1, w310, ps0[mi * 2 + rh]));
                        ps1[mi * 2 + rh] = fmaf(v0, w301, fmaf(v1, w311, ps1[mi * 2 + rh]));
                    }
                }
            }
        }
        __syncthreads();
    }

    // ---- layer-3 reduction via shared atomics ----
    #pragma unroll
    for (int mi = 0; mi < 4; ++mi)
        #pragma unroll
        for (int rh = 0; rh < 2; ++rh) {
            int p = mi * 16 + (lid >> 2) + rh * 8;
            atomicAdd(&par[PF_RED + p * 2 + 0], ps0[mi * 2 + rh]);
            atomicAdd(&par[PF_RED + p * 2 + 1], ps1[mi * 2 + rh]);
        }
    __syncthreads();

    if (tid < 128) {
        int p = tid >> 1;
        int o = tid & 1;
        float cc = par[PF_CS + p];
        float q0 = par[PF_YPX + p], q1 = par[PF_YPY + p];
        float s = par[PF_RED + p * 2 + o];
        s += q0 * par[PF_W3 + 512 + o] + q1 * par[PF_W3 + 514 + o];
        float v = s + par[PF_W3 + 516 + o];
        float g = sigmoidf_fast(cc * par[PF_W3 + 518 + o] + par[PF_W3 + 520 + o]);
        v = g * v + cc * par[PF_W3 + 522 + o];
        out_g[((size_t)b * NN + p0 + p) * 2 + o] = v;
    }
}

extern "C" void kernel_launch(void* const* d_in, const int* in_sizes, int n_in,
                              void* d_out, int out_size) {
    (void)in_sizes; (void)n_in; (void)out_size;
    const float* ctx = (const float*)d_in[0];
    const float* y   = (const float*)d_in[1];
    const float* yp  = (const float*)d_in[2];
    const float* tnw = (const float*)d_in[3];
    float* out = (float*)d_out;

    prep_weights_kernel<<<128, 256>>>(tnw);

    cudaFuncSetAttribute(ode_hypernet_mma_kernel,
                         cudaFuncAttributeMaxDynamicSharedMemorySize, SMEM_TOTAL);
    dim3 grid(NN / TP, BB);   // (32, 64)
    ode_hypernet_mma_kernel<<<grid, 256, SMEM_TOTAL>>>(ctx, y, yp, tnw, out);
}

// round 9
// speedup vs baseline: 6.2838x; 1.0538x over previous
#include <cuda_runtime.h>
#include <cuda_fp16.h>
#include <cstdint>

typedef unsigned int u32;

// ---------------- problem constants ----------------
#define BB 64
#define NN 2048
#define TW 136716
#define TP 64

// ---------------- smem layout (bytes) ----------------
#define SM_A   0          // A fp16 frag-major: [4 m16][16 k16][32 lid][16B] = 32768
#define SM_B   32768      // 2 bufs x 32768; each buf = 2 kc chunks of 16KB
#define SM_PAR 98304
// float offsets inside PAR
#define PF_FILM  0
#define PF_WTAIL 1024
#define PF_W3    1536
#define PF_CS    2064
#define PF_YPX   2128
#define PF_YPY   2192
#define PF_YS    2256
#define PF_W0    2384
#define PF_RED   3408
#define SMEM_TOTAL (98304 + 3536*4)   // 112448

#define BSCALE     1024.0f
#define INV_BSCALE 0.0009765625f

// precomputed fp16 weights, frag-major: [b][l][kc 8][4096 u32] = 16 MB used
__device__ uint4 g_wbf[2097152];

// ---------------- helpers ----------------
__device__ __forceinline__ u32 smem_u32(const void* p) {
    u32 a; asm("{ .reg .u64 t; cvta.to.shared.u64 t, %1; cvt.u32.u64 %0, t; }" : "=r"(a) : "l"(p));
    return a;
}
__device__ __forceinline__ u32 pack_h2(float a, float b) {
    __half2 t = __floats2half2_rn(a, b);
    return *reinterpret_cast<u32*>(&t);
}
__device__ __forceinline__ void lds128(u32& r0, u32& r1, u32& r2, u32& r3, u32 addr) {
    asm volatile("ld.shared.v4.u32 {%0,%1,%2,%3}, [%4];"
                 : "=r"(r0), "=r"(r1), "=r"(r2), "=r"(r3) : "r"(addr));
}
__device__ __forceinline__ void mmaf16(float& c0, float& c1, float& c2, float& c3,
                                       u32 a0, u32 a1, u32 a2, u32 a3,
                                       u32 b0, u32 b1) {
    asm volatile("mma.sync.aligned.m16n8k16.row.col.f32.f16.f16.f32 "
                 "{%0,%1,%2,%3}, {%4,%5,%6,%7}, {%8,%9}, {%0,%1,%2,%3};"
                 : "+f"(c0), "+f"(c1), "+f"(c2), "+f"(c3)
                 : "r"(a0), "r"(a1), "r"(a2), "r"(a3), "r"(b0), "r"(b1));
}
__device__ __forceinline__ void cpasync16(u32 dst, const void* src) {
    asm volatile("cp.async.cg.shared.global [%0], [%1], 16;" :: "r"(dst), "l"(src));
}
#define CP_COMMIT() asm volatile("cp.async.commit_group;" ::: "memory")
#define CP_WAIT0()  asm volatile("cp.async.wait_group 0;" ::: "memory")

__device__ __forceinline__ float ex2f(float x){ float r; asm("ex2.approx.ftz.f32 %0, %1;" : "=f"(r) : "f"(x)); return r; }
__device__ __forceinline__ float lg2f(float x){ float r; asm("lg2.approx.ftz.f32 %0, %1;" : "=f"(r) : "f"(x)); return r; }
__device__ __forceinline__ float tanhf_fast(float x){ float r; asm("tanh.approx.f32 %0, %1;" : "=f"(r) : "f"(x)); return r; }
// sigmoid(x) = 0.5 + 0.5*tanh(x/2); caller passes halfarg = x/2 (FiLM params pre-halved)
__device__ __forceinline__ float sigmoid_ht(float halfarg) {
    return fmaf(tanhf_fast(halfarg), 0.5f, 0.5f);
}
__device__ __forceinline__ float softplusf_fast(float x) {
    float e = ex2f(-1.4426950408889634f * fabsf(x));
    return fmaxf(x, 0.0f) + 0.6931471805599453f * lg2f(1.0f + e);
}

// ---------------- prep: f32 W -> fp16 (x1024) frag-major image ----------------
__global__ __launch_bounds__(256)
void prep_weights_kernel(const float* __restrict__ tnw)
{
    __shared__ float s[32][257];
    int bl = blockIdx.x;           // 0..127
    int l = bl & 1, b = bl >> 1;
    const float* wl = tnw + (size_t)b * TW + (l == 0 ? 2048 : 69120);
    int t = threadIdx.x;
    u32* gh = (u32*)g_wbf;

    for (int kc = 0; kc < 8; ++kc) {
        __syncthreads();
        #pragma unroll
        for (int j = 0; j < 32; ++j) {
            int idx = t + j * 256;               // 8192 floats
            int r = idx >> 8, c = idx & 255;
            s[r][c] = wl[(size_t)(kc * 32 + r) * 256 + c];
        }
        __syncthreads();
        size_t base0 = ((size_t)(b * 2 + l) * 8 + kc) * 4096;
        #pragma unroll
        for (int j = 0; j < 16; ++j) {
            int idx = t + j * 256;               // 0..4095
            int reg = idx & 3;
            int lid = (idx >> 2) & 31;
            int n16 = (idx >> 7) & 15;
            int ks  = idx >> 11;
            int koff = ks * 16 + 2 * (lid & 3) + 8 * (reg & 1);
            int n = n16 * 16 + (lid >> 2) + 8 * (reg >> 1);
            gh[base0 + idx] = pack_h2(s[koff][n] * BSCALE, s[koff + 1][n] * BSCALE);
        }
    }
}

// ---------------- main kernel: 256 threads, 8 warps (64x32 warp tiles), 2 CTAs/SM ----------------
__global__ __launch_bounds__(256, 2)
void ode_hypernet_mma_kernel(const float* __restrict__ ctx_g,
                             const float* __restrict__ y_g,
                             const float* __restrict__ yp_g,
                             const float* __restrict__ tnw_g,
                             float* __restrict__ out_g)
{
    extern __shared__ char smc[];
    float* par = (float*)(smc + SM_PAR);
    const u32 smb = smem_u32(smc);

    const int tid = threadIdx.x;
    const int lid = tid & 31;
    const int wid = tid >> 5;        // = wn, 8 warps x 32 cols
    const int b  = blockIdx.y;
    const int p0 = blockIdx.x * TP;
    const float* w = tnw_g + (size_t)b * TW;
    const char* gw = (const char*)g_wbf;

    // item stream: g 0..7 -> layer (g>>2), kc-pair (g&3), buf (g&1); 32KB per item
    auto load_chunk_g = [&](int g) {
        size_t src = ((size_t)(b * 2 + (g >> 2)) * 8 + (size_t)(g & 3) * 2) * 16384;
        u32 dbase = smb + SM_B + (u32)(g & 1) * 32768;
        #pragma unroll
        for (int i = 0; i < 8; ++i) {
            u32 off = (u32)(tid + i * 256) * 16;
            cpasync16(dbase + off, gw + src + off);
        }
        CP_COMMIT();
    };

    // ---- initial loads (film wsc/bsc pre-halved for tanh-sigmoid) ----
    if (tid < 64) {
        par[PF_CS + tid] = ctx_g[(size_t)b * NN + p0 + tid];
        size_t base = ((size_t)b * NN + p0 + tid) * 2;
        par[PF_YPX + tid] = yp_g[base + 0];
        par[PF_YPY + tid] = yp_g[base + 1];
    }
    if (tid < 128) par[PF_YS + tid] = y_g[((size_t)b * NN + p0) * 2 + tid];
    #pragma unroll
    for (int i = 0; i < 4; ++i) par[PF_W0 + i * 256 + tid] = w[i * 256 + tid];
    #pragma unroll
    for (int i = 0; i < 4; ++i) {
        float scale = (i == 1 || i == 2) ? 0.5f : 1.0f;   // wscale, bscale halved
        par[PF_FILM + i * 256 + tid] = w[1024 + i * 256 + tid] * scale;
    }
    for (int i = tid; i < 524; i += 256) par[PF_W3 + i] = w[136192 + i];

    load_chunk_g(0);
    __syncthreads();

    // ---- layer 0 (SIMT): 4 -> 256, FiLM + softplus, write A fp16 frag-major ----
    {
        int p = tid & 63;
        int h2 = tid >> 6;           // 0..3, 64 channels each
        float y0 = par[PF_YS + 2 * p], y1 = par[PF_YS + 2 * p + 1];
        float q0 = par[PF_YPX + p],    q1 = par[PF_YPY + p];
        float cc = par[PF_CS + p];
        int m16 = p >> 4;
        int plid4 = (p & 7) * 4;
        int preg = (p >> 3) & 1;
        #pragma unroll 4
        for (int j = 0; j < 32; ++j) {
            int ch = h2 * 64 + 2 * j;
            float v0 = y0 * par[PF_W0 + ch]       + y1 * par[PF_W0 + 256 + ch]
                     + q0 * par[PF_W0 + 512 + ch] + q1 * par[PF_W0 + 768 + ch]
                     + par[PF_FILM + ch];
            float v1 = y0 * par[PF_W0 + ch + 1]       + y1 * par[PF_W0 + 256 + ch + 1]
                     + q0 * par[PF_W0 + 512 + ch + 1] + q1 * par[PF_W0 + 768 + ch + 1]
                     + par[PF_FILM + ch + 1];
            float s0 = sigmoid_ht(cc * par[PF_FILM + 256 + ch]     + par[PF_FILM + 512 + ch]);
            float s1 = sigmoid_ht(cc * par[PF_FILM + 256 + ch + 1] + par[PF_FILM + 512 + ch + 1]);
            v0 = s0 * v0 + cc * par[PF_FILM + 768 + ch];
            v1 = s1 * v1 + cc * par[PF_FILM + 768 + ch + 1];
            v0 = softplusf_fast(v0);
            v1 = softplusf_fast(v1);
            int k16 = ch >> 4;
            int flid = plid4 + (j & 3);
            int reg  = preg + 2 * ((j >> 2) & 1);
            u32 off = (u32)((m16 * 16 + k16) * 32 + flid) * 16 + (u32)reg * 4;
            *(u32*)(smc + SM_A + off) = pack_h2(v0, v1);
        }
    }
    CP_WAIT0();
    __syncthreads();

    float ps0[8], ps1[8];            // layer-3 partials (mi x rh)

    #pragma unroll 1
    for (int l = 1; l <= 2; ++l) {
        const float* wl = w + ((l == 1) ? 2048 : 69120);
        const float* fp = wl + 66048;
        #pragma unroll
        for (int i = 0; i < 4; ++i) {
            float scale = (i == 1 || i == 2) ? 0.5f : 1.0f;   // pre-halve for tanh
            par[PF_FILM + i * 256 + tid] = fp[i * 256 + tid] * scale;
        }
        par[PF_WTAIL + tid]       = wl[65536 + tid];
        par[PF_WTAIL + 256 + tid] = wl[65792 + tid];

        float acc[4][4][4];
        #pragma unroll
        for (int mi = 0; mi < 4; ++mi)
            #pragma unroll
            for (int n8 = 0; n8 < 4; ++n8)
                #pragma unroll
                for (int q = 0; q < 4; ++q) acc[mi][n8][q] = 0.0f;

        #pragma unroll 1
        for (int item = 0; item < 4; ++item) {
            int g = (l - 1) * 4 + item;
            int buf = g & 1;
            if (g < 7) load_chunk_g(g + 1);

            u32 bbuf = smb + SM_B + (u32)buf * 32768;
            #pragma unroll
            for (int kc2 = 0; kc2 < 2; ++kc2) {
                #pragma unroll
                for (int ks = 0; ks < 2; ++ks) {
                    int k16 = item * 4 + kc2 * 2 + ks;
                    // A frags: 4 x LDS.128 (fp16, frag-major)
                    u32 a[4][4];
                    #pragma unroll
                    for (int mi = 0; mi < 4; ++mi)
                        lds128(a[mi][0], a[mi][1], a[mi][2], a[mi][3],
                               smb + SM_A + (u32)((mi * 16 + k16) * 32 + lid) * 16);
                    // B frags: 2 n16-groups
                    u32 bh[2][4];
                    #pragma unroll
                    for (int nt = 0; nt < 2; ++nt) {
                        u32 off = (u32)kc2 * 16384
                                + (u32)((ks * 16 + wid * 2 + nt) * 32 + lid) * 16;
                        lds128(bh[nt][0], bh[nt][1], bh[nt][2], bh[nt][3], bbuf + off);
                    }
                    #pragma unroll
                    for (int mi = 0; mi < 4; ++mi)
                        #pragma unroll
                        for (int n8 = 0; n8 < 4; ++n8) {
                            int nt = n8 >> 1, pp = (n8 & 1) * 2;
                            mmaf16(acc[mi][n8][0], acc[mi][n8][1], acc[mi][n8][2], acc[mi][n8][3],
                                   a[mi][0], a[mi][1], a[mi][2], a[mi][3],
                                   bh[nt][pp], bh[nt][pp + 1]);
                        }
                }
            }
            CP_WAIT0();
            __syncthreads();
        }

        if (l == 2) {
            if (tid < 128) par[PF_RED + tid] = 0.0f;
            #pragma unroll
            for (int i = 0; i < 8; ++i) { ps0[i] = 0.0f; ps1[i] = 0.0f; }
            __syncthreads();
        }

        // ---- epilogue: FiLM + softplus ----
        #pragma unroll
        for (int n8 = 0; n8 < 4; ++n8) {
            int col0 = wid * 32 + n8 * 8 + (lid & 3) * 2;
            int col1 = col0 + 1;
            float bi0  = par[PF_FILM + col0],       bi1  = par[PF_FILM + col1];
            float wsc0 = par[PF_FILM + 256 + col0], wsc1 = par[PF_FILM + 256 + col1];
            float bsc0 = par[PF_FILM + 512 + col0], bsc1 = par[PF_FILM + 512 + col1];
            float wsh0 = par[PF_FILM + 768 + col0], wsh1 = par[PF_FILM + 768 + col1];
            float wt00 = par[PF_WTAIL + col0],       wt01 = par[PF_WTAIL + col1];
            float wt10 = par[PF_WTAIL + 256 + col0], wt11 = par[PF_WTAIL + 256 + col1];
            float w300 = 0.f, w301 = 0.f, w310 = 0.f, w311 = 0.f;
            if (l == 2) {
                w300 = par[PF_W3 + 2 * col0];     w301 = par[PF_W3 + 2 * col0 + 1];
                w310 = par[PF_W3 + 2 * col1];     w311 = par[PF_W3 + 2 * col1 + 1];
            }
            int k16n = wid * 2 + (n8 >> 1);     // next-layer k16 of this col pair
            #pragma unroll
            for (int mi = 0; mi < 4; ++mi) {
                #pragma unroll
                for (int rh = 0; rh < 2; ++rh) {
                    int row = mi * 16 + (lid >> 2) + rh * 8;
                    float cc = par[PF_CS + row];
                    float q0 = par[PF_YPX + row], q1 = par[PF_YPY + row];
                    float v0 = acc[mi][n8][rh * 2 + 0] * INV_BSCALE;
                    float v1 = acc[mi][n8][rh * 2 + 1] * INV_BSCALE;
                    v0 += bi0 + q0 * wt00 + q1 * wt10;
                    v1 += bi1 + q0 * wt01 + q1 * wt11;
                    float s0 = sigmoid_ht(cc * wsc0 + bsc0);
                    float s1 = sigmoid_ht(cc * wsc1 + bsc1);
                    v0 = s0 * v0 + cc * wsh0;
                    v1 = s1 * v1 + cc * wsh1;
                    v0 = softplusf_fast(v0);
                    v1 = softplusf_fast(v1);
                    if (l == 1) {
                        u32 off = (u32)((mi * 16 + k16n) * 32 + lid) * 16
                                + (u32)(rh + 2 * (n8 & 1)) * 4;
                        *(u32*)(smc + SM_A + off) = pack_h2(v0, v1);
                    } else {
                        ps0[mi * 2 + rh] = fmaf(v0, w300, fmaf(v1, w310, ps0[mi * 2 + rh]));
                        ps1[mi * 2 + rh] = fmaf(v0, w301, fmaf(v1, w311, ps1[mi * 2 + rh]));
                    }
                }
            }
        }
        __syncthreads();
    }

    // ---- layer-3 reduction via shared atomics ----
    #pragma unroll
    for (int mi = 0; mi < 4; ++mi)
        #pragma unroll
        for (int rh = 0; rh < 2; ++rh) {
            int p = mi * 16 + (lid >> 2) + rh * 8;
            atomicAdd(&par[PF_RED + p * 2 + 0], ps0[mi * 2 + rh]);
            atomicAdd(&par[PF_RED + p * 2 + 1], ps1[mi * 2 + rh]);
        }
    __syncthreads();

    if (tid < 128) {
        int p = tid >> 1;
        int o = tid & 1;
        float cc = par[PF_CS + p];
        float q0 = par[PF_YPX + p], q1 = par[PF_YPY + p];
        float s = par[PF_RED + p * 2 + o];
        s += q0 * par[PF_W3 + 512 + o] + q1 * par[PF_W3 + 514 + o];
        float v = s + par[PF_W3 + 516 + o];
        float g = sigmoid_ht(0.5f * (cc * par[PF_W3 + 518 + o] + par[PF_W3 + 520 + o]));
        v = g * v + cc * par[PF_W3 + 522 + o];
        out_g[((size_t)b * NN + p0 + p) * 2 + o] = v;
    }
}

extern "C" void kernel_launch(void* const* d_in, const int* in_sizes, int n_in,
                              void* d_out, int out_size) {
    (void)in_sizes; (void)n_in; (void)out_size;
    const float* ctx = (const float*)d_in[0];
    const float* y   = (const float*)d_in[1];
    const float* yp  = (const float*)d_in[2];
    const float* tnw = (const float*)d_in[3];
    float* out = (float*)d_out;

    prep_weights_kernel<<<128, 256>>>(tnw);

    cudaFuncSetAttribute(ode_hypernet_mma_kernel,
                         cudaFuncAttributeMaxDynamicSharedMemorySize, SMEM_TOTAL);
    dim3 grid(NN / TP, BB);   // (32, 64)
    ode_hypernet_mma_kernel<<<grid, 256, SMEM_TOTAL>>>(ctx, y, yp, tnw, out);
}